// round 2
// baseline (speedup 1.0000x reference)
#include <cuda_runtime.h>

// Problem constants (fixed shapes from reference)
#define TOK   (4 * 4096)   // B*S = 16384 tokens
#define HDIM  2048

// Scratch: compacted intermediates (max 1024 cols needed per token)
__device__ float g_bufA[(size_t)TOK * 1024];  // 64 MB
__device__ float g_bufB[(size_t)TOK * 1024];  // 64 MB
__device__ int   g_idx1[TOK];
__device__ int   g_idx2[TOK];
__device__ int   g_cnt[2];

// ---------------------------------------------------------------------------
__global__ void k_init_counters() {
    g_cnt[0] = 0;
    g_cnt[1] = 0;
}

// out = hidden_states (default for selected==0; branch scatters overwrite)
__global__ void k_copy4(const float* __restrict__ src, float* __restrict__ dst, int n4) {
    int i = blockIdx.x * blockDim.x + threadIdx.x;
    if (i < n4) ((float4*)dst)[i] = ((const float4*)src)[i];
}

// Per-token: logits = sel2_W @ hid + b2 ; argmax ; compact indices for branches 1/2.
// One warp per token.
__global__ void k_argmax_compact(const float* __restrict__ hid,      // [TOK, 512]
                                 const float* __restrict__ W2,       // [3, 512]
                                 const float* __restrict__ b2) {     // [3]
    int t = blockIdx.x * blockDim.x + threadIdx.x;
    int tok = t >> 5, lane = t & 31;
    if (tok >= TOK) return;
    const float* hrow = hid + (size_t)tok * 512;
    float s0 = 0.f, s1 = 0.f, s2 = 0.f;
    #pragma unroll 4
    for (int k = lane; k < 512; k += 32) {
        float v = hrow[k];
        s0 += v * W2[k];
        s1 += v * W2[512 + k];
        s2 += v * W2[1024 + k];
    }
    #pragma unroll
    for (int o = 16; o; o >>= 1) {
        s0 += __shfl_down_sync(0xffffffffu, s0, o);
        s1 += __shfl_down_sync(0xffffffffu, s1, o);
        s2 += __shfl_down_sync(0xffffffffu, s2, o);
    }
    if (lane == 0) {
        s0 += b2[0]; s1 += b2[1]; s2 += b2[2];
        // jnp.argmax takes the FIRST max -> strict '>' comparisons
        int sel = 0; float best = s0;
        if (s1 > best) { best = s1; sel = 1; }
        if (s2 > best) { best = s2; sel = 2; }
        if (sel == 1)      { int p = atomicAdd(&g_cnt[0], 1); g_idx1[p] = tok; }
        else if (sel == 2) { int p = atomicAdd(&g_cnt[1], 1); g_idx2[p] = tok; }
    }
}

// ---------------------------------------------------------------------------
// NT GEMM:  C[m, n] = sum_k A[row(m), k] * W[n, k] + bias[n]   (optional ReLU)
//   - A rows optionally gathered through `gather` (compaction)
//   - C rows optionally scattered through `scatter`
//   - M optionally dynamic (*cntp), blocks past M early-exit
//   - optional per-token modulation of A: k < K/2 scaled by freq[row], else imp[row]
// Tile: 128x128, BK=16, 256 threads, 8x8 per-thread microtile.
// ---------------------------------------------------------------------------
__global__ __launch_bounds__(256, 2)
void k_gemm128(const float* __restrict__ A, const float* __restrict__ W,
               const float* __restrict__ bias, float* __restrict__ C,
               int M, const int* __restrict__ cntp, int K,
               const int* __restrict__ gather, const int* __restrict__ scatter,
               int ldc,
               const float* __restrict__ freq, const float* __restrict__ imp,
               int relu)
{
    if (cntp) M = *cntp;
    const int tileM = blockIdx.y * 128;
    if (tileM >= M) return;
    const int tileN = blockIdx.x * 128;

    __shared__ float As[16][128];
    __shared__ float Bs[16][128];

    const int tid = threadIdx.x;
    const int tx = tid & 15;   // 16 col groups of 8
    const int ty = tid >> 4;   // 16 row groups of 8

    // Load mapping: 512 float4 per 128x16 tile; this thread handles float4 ids
    // v0=tid (row r0=tid>>2), v1=tid+256 (row r0+64); kk = float4 slot within row.
    const int kk = tid & 3;
    const int r0 = tid >> 2;
    const int r1 = r0 + 64;

    const int m0 = tileM + r0;
    const int m1 = tileM + r1;
    const bool v0 = (m0 < M);
    const bool v1 = (m1 < M);
    const int gr0 = v0 ? (gather ? gather[m0] : m0) : 0;
    const int gr1 = v1 ? (gather ? gather[m1] : m1) : 0;
    const float* a0p = A + (size_t)gr0 * K;
    const float* a1p = A + (size_t)gr1 * K;
    float fr0 = 1.f, im0 = 1.f, fr1 = 1.f, im1 = 1.f;
    if (freq) { fr0 = freq[gr0]; im0 = imp[gr0]; fr1 = freq[gr1]; im1 = imp[gr1]; }

    const float* w0p = W + (size_t)(tileN + r0) * K;
    const float* w1p = W + (size_t)(tileN + r1) * K;

    float acc[8][8];
    #pragma unroll
    for (int i = 0; i < 8; i++)
        #pragma unroll
        for (int j = 0; j < 8; j++) acc[i][j] = 0.f;

    const int halfK = K >> 1;

    for (int k0 = 0; k0 < K; k0 += 16) {
        const int kc = k0 + kk * 4;
        float4 av0 = v0 ? *(const float4*)(a0p + kc) : make_float4(0.f, 0.f, 0.f, 0.f);
        float4 av1 = v1 ? *(const float4*)(a1p + kc) : make_float4(0.f, 0.f, 0.f, 0.f);
        if (freq) {
            float s0 = (kc < halfK) ? fr0 : im0;
            float s1 = (kc < halfK) ? fr1 : im1;
            av0.x *= s0; av0.y *= s0; av0.z *= s0; av0.w *= s0;
            av1.x *= s1; av1.y *= s1; av1.z *= s1; av1.w *= s1;
        }
        float4 bv0 = *(const float4*)(w0p + kc);
        float4 bv1 = *(const float4*)(w1p + kc);

        As[kk * 4 + 0][r0] = av0.x; As[kk * 4 + 1][r0] = av0.y;
        As[kk * 4 + 2][r0] = av0.z; As[kk * 4 + 3][r0] = av0.w;
        As[kk * 4 + 0][r1] = av1.x; As[kk * 4 + 1][r1] = av1.y;
        As[kk * 4 + 2][r1] = av1.z; As[kk * 4 + 3][r1] = av1.w;
        Bs[kk * 4 + 0][r0] = bv0.x; Bs[kk * 4 + 1][r0] = bv0.y;
        Bs[kk * 4 + 2][r0] = bv0.z; Bs[kk * 4 + 3][r0] = bv0.w;
        Bs[kk * 4 + 0][r1] = bv1.x; Bs[kk * 4 + 1][r1] = bv1.y;
        Bs[kk * 4 + 2][r1] = bv1.z; Bs[kk * 4 + 3][r1] = bv1.w;
        __syncthreads();

        #pragma unroll
        for (int k = 0; k < 16; k++) {
            float4 aq0 = *(const float4*)&As[k][ty * 8];
            float4 aq1 = *(const float4*)&As[k][ty * 8 + 4];
            float4 bq0 = *(const float4*)&Bs[k][tx * 8];
            float4 bq1 = *(const float4*)&Bs[k][tx * 8 + 4];
            float ar[8] = {aq0.x, aq0.y, aq0.z, aq0.w, aq1.x, aq1.y, aq1.z, aq1.w};
            float br[8] = {bq0.x, bq0.y, bq0.z, bq0.w, bq1.x, bq1.y, bq1.z, bq1.w};
            #pragma unroll
            for (int i = 0; i < 8; i++)
                #pragma unroll
                for (int j = 0; j < 8; j++)
                    acc[i][j] = fmaf(ar[i], br[j], acc[i][j]);
        }
        __syncthreads();
    }

    // Epilogue: bias (+ReLU), optional row scatter, float4 stores
    const int ncol = tileN + tx * 8;
    float4 bb0 = *(const float4*)(bias + ncol);
    float4 bb1 = *(const float4*)(bias + ncol + 4);
    #pragma unroll
    for (int i = 0; i < 8; i++) {
        int m = tileM + ty * 8 + i;
        if (m >= M) continue;
        int cr = scatter ? scatter[m] : m;
        float* crow = C + (size_t)cr * ldc + ncol;
        float4 o0, o1;
        o0.x = acc[i][0] + bb0.x; o0.y = acc[i][1] + bb0.y;
        o0.z = acc[i][2] + bb0.z; o0.w = acc[i][3] + bb0.w;
        o1.x = acc[i][4] + bb1.x; o1.y = acc[i][5] + bb1.y;
        o1.z = acc[i][6] + bb1.z; o1.w = acc[i][7] + bb1.w;
        if (relu) {
            o0.x = fmaxf(o0.x, 0.f); o0.y = fmaxf(o0.y, 0.f);
            o0.z = fmaxf(o0.z, 0.f); o0.w = fmaxf(o0.w, 0.f);
            o1.x = fmaxf(o1.x, 0.f); o1.y = fmaxf(o1.y, 0.f);
            o1.z = fmaxf(o1.z, 0.f); o1.w = fmaxf(o1.w, 0.f);
        }
        *(float4*)(crow)     = o0;
        *(float4*)(crow + 4) = o1;
    }
}

// ---------------------------------------------------------------------------
extern "C" void kernel_launch(void* const* d_in, const int* in_sizes, int n_in,
                              void* d_out, int out_size)
{
    const float* h       = (const float*)d_in[0];   // [4,4096,2048]
    const float* freq    = (const float*)d_in[1];   // [4,4096]
    const float* imp     = (const float*)d_in[2];   // [4,4096]
    const float* comp1_W = (const float*)d_in[3];   // [1024,2048]
    const float* comp1_b = (const float*)d_in[4];
    const float* adpt1_W = (const float*)d_in[5];   // [1024,1024]
    const float* adpt1_b = (const float*)d_in[6];
    const float* dec1_W  = (const float*)d_in[7];   // [2048,1024]
    const float* dec1_b  = (const float*)d_in[8];
    const float* comp2_W = (const float*)d_in[9];   // [512,2048]
    const float* comp2_b = (const float*)d_in[10];
    const float* adpt2_W = (const float*)d_in[11];  // [512,512]
    const float* adpt2_b = (const float*)d_in[12];
    const float* dec2_W  = (const float*)d_in[13];  // [2048,512]
    const float* dec2_b  = (const float*)d_in[14];
    const float* sel1_W  = (const float*)d_in[15];  // [512,2048]
    const float* sel1_b  = (const float*)d_in[16];
    const float* sel2_W  = (const float*)d_in[17];  // [3,512]
    const float* sel2_b  = (const float*)d_in[18];
    float* out = (float*)d_out;

    float *bufA, *bufB; int *idx1, *idx2, *cnt;
    cudaGetSymbolAddress((void**)&bufA, g_bufA);
    cudaGetSymbolAddress((void**)&bufB, g_bufB);
    cudaGetSymbolAddress((void**)&idx1, g_idx1);
    cudaGetSymbolAddress((void**)&idx2, g_idx2);
    cudaGetSymbolAddress((void**)&cnt,  g_cnt);

    const int MAXY = TOK / 128;  // 128 m-tiles

    k_init_counters<<<1, 32>>>();

    // out = h (covers selected==0; branches overwrite their rows)
    {
        int n4 = TOK * HDIM / 4;
        k_copy4<<<(n4 + 255) / 256, 256>>>(h, out, n4);
    }

    // selector hidden: relu(modulated_h @ sel1_W^T + b) -> bufA [TOK,512]
    k_gemm128<<<dim3(512 / 128, MAXY), 256>>>(h, sel1_W, sel1_b, bufA,
        TOK, nullptr, HDIM, nullptr, nullptr, 512, freq, imp, 1);

    // logits + argmax + index compaction
    k_argmax_compact<<<(TOK * 32 + 255) / 256, 256>>>(bufA, sel2_W, sel2_b);

    // ---- branch 1 (tokens with selected==1), compacted ----
    k_gemm128<<<dim3(1024 / 128, MAXY), 256>>>(h, comp1_W, comp1_b, bufB,
        TOK, &cnt[0], HDIM, idx1, nullptr, 1024, nullptr, nullptr, 0);
    k_gemm128<<<dim3(1024 / 128, MAXY), 256>>>(bufB, adpt1_W, adpt1_b, bufA,
        TOK, &cnt[0], 1024, nullptr, nullptr, 1024, nullptr, nullptr, 0);
    k_gemm128<<<dim3(2048 / 128, MAXY), 256>>>(bufA, dec1_W, dec1_b, out,
        TOK, &cnt[0], 1024, nullptr, idx1, HDIM, nullptr, nullptr, 0);

    // ---- branch 2 (tokens with selected==2), compacted ----
    k_gemm128<<<dim3(512 / 128, MAXY), 256>>>(h, comp2_W, comp2_b, bufB,
        TOK, &cnt[1], HDIM, idx2, nullptr, 512, nullptr, nullptr, 0);
    k_gemm128<<<dim3(512 / 128, MAXY), 256>>>(bufB, adpt2_W, adpt2_b, bufA,
        TOK, &cnt[1], 512, nullptr, nullptr, 512, nullptr, nullptr, 0);
    k_gemm128<<<dim3(2048 / 128, MAXY), 256>>>(bufA, dec2_W, dec2_b, out,
        TOK, &cnt[1], 512, nullptr, idx2, HDIM, nullptr, nullptr, 0);
}

// round 3
// speedup vs baseline: 1.5249x; 1.5249x over previous
#include <cuda_runtime.h>

// Problem constants (fixed shapes from reference)
#define TOK   (4 * 4096)   // B*S = 16384 tokens
#define HDIM  2048

// Scratch: compacted intermediates (max 1024 cols needed per token)
__device__ float g_bufA[(size_t)TOK * 1024];  // 64 MB
__device__ float g_bufB[(size_t)TOK * 1024];  // 64 MB
__device__ int   g_idx1[TOK];
__device__ int   g_idx2[TOK];
__device__ int   g_cnt[2];

// ---------------------------------------------------------------------------
__global__ void k_init_counters() {
    g_cnt[0] = 0;
    g_cnt[1] = 0;
}

// out = hidden_states (default for selected==0; branch scatters overwrite)
__global__ void k_copy4(const float* __restrict__ src, float* __restrict__ dst, int n4) {
    int i = blockIdx.x * blockDim.x + threadIdx.x;
    if (i < n4) ((float4*)dst)[i] = ((const float4*)src)[i];
}

// Per-token: logits = sel2_W @ hid + b2 ; argmax ; compact indices for branches 1/2.
// One warp per token.
__global__ void k_argmax_compact(const float* __restrict__ hid,      // [TOK, 512]
                                 const float* __restrict__ W2,       // [3, 512]
                                 const float* __restrict__ b2) {     // [3]
    int t = blockIdx.x * blockDim.x + threadIdx.x;
    int tok = t >> 5, lane = t & 31;
    if (tok >= TOK) return;
    const float* hrow = hid + (size_t)tok * 512;
    float s0 = 0.f, s1 = 0.f, s2 = 0.f;
    #pragma unroll 4
    for (int k = lane; k < 512; k += 32) {
        float v = hrow[k];
        s0 += v * W2[k];
        s1 += v * W2[512 + k];
        s2 += v * W2[1024 + k];
    }
    #pragma unroll
    for (int o = 16; o; o >>= 1) {
        s0 += __shfl_down_sync(0xffffffffu, s0, o);
        s1 += __shfl_down_sync(0xffffffffu, s1, o);
        s2 += __shfl_down_sync(0xffffffffu, s2, o);
    }
    if (lane == 0) {
        s0 += b2[0]; s1 += b2[1]; s2 += b2[2];
        // jnp.argmax takes the FIRST max -> strict '>' comparisons
        int sel = 0; float best = s0;
        if (s1 > best) { best = s1; sel = 1; }
        if (s2 > best) { best = s2; sel = 2; }
        if (sel == 1)      { int p = atomicAdd(&g_cnt[0], 1); g_idx1[p] = tok; }
        else if (sel == 2) { int p = atomicAdd(&g_cnt[1], 1); g_idx2[p] = tok; }
    }
}

// ---------------------------------------------------------------------------
// fp32 SIMT NT GEMM (kept for the selector: argmax decisions must stay exact)
// ---------------------------------------------------------------------------
__global__ __launch_bounds__(256, 2)
void k_gemm128(const float* __restrict__ A, const float* __restrict__ W,
               const float* __restrict__ bias, float* __restrict__ C,
               int M, const int* __restrict__ cntp, int K,
               const int* __restrict__ gather, const int* __restrict__ scatter,
               int ldc,
               const float* __restrict__ freq, const float* __restrict__ imp,
               int relu)
{
    if (cntp) M = *cntp;
    const int tileM = blockIdx.y * 128;
    if (tileM >= M) return;
    const int tileN = blockIdx.x * 128;

    __shared__ float As[16][128];
    __shared__ float Bs[16][128];

    const int tid = threadIdx.x;
    const int tx = tid & 15;
    const int ty = tid >> 4;

    const int kk = tid & 3;
    const int r0 = tid >> 2;
    const int r1 = r0 + 64;

    const int m0 = tileM + r0;
    const int m1 = tileM + r1;
    const bool v0 = (m0 < M);
    const bool v1 = (m1 < M);
    const int gr0 = v0 ? (gather ? gather[m0] : m0) : 0;
    const int gr1 = v1 ? (gather ? gather[m1] : m1) : 0;
    const float* a0p = A + (size_t)gr0 * K;
    const float* a1p = A + (size_t)gr1 * K;
    float fr0 = 1.f, im0 = 1.f, fr1 = 1.f, im1 = 1.f;
    if (freq) { fr0 = freq[gr0]; im0 = imp[gr0]; fr1 = freq[gr1]; im1 = imp[gr1]; }

    const float* w0p = W + (size_t)(tileN + r0) * K;
    const float* w1p = W + (size_t)(tileN + r1) * K;

    float acc[8][8];
    #pragma unroll
    for (int i = 0; i < 8; i++)
        #pragma unroll
        for (int j = 0; j < 8; j++) acc[i][j] = 0.f;

    const int halfK = K >> 1;

    for (int k0 = 0; k0 < K; k0 += 16) {
        const int kc = k0 + kk * 4;
        float4 av0 = v0 ? *(const float4*)(a0p + kc) : make_float4(0.f, 0.f, 0.f, 0.f);
        float4 av1 = v1 ? *(const float4*)(a1p + kc) : make_float4(0.f, 0.f, 0.f, 0.f);
        if (freq) {
            float s0 = (kc < halfK) ? fr0 : im0;
            float s1 = (kc < halfK) ? fr1 : im1;
            av0.x *= s0; av0.y *= s0; av0.z *= s0; av0.w *= s0;
            av1.x *= s1; av1.y *= s1; av1.z *= s1; av1.w *= s1;
        }
        float4 bv0 = *(const float4*)(w0p + kc);
        float4 bv1 = *(const float4*)(w1p + kc);

        As[kk * 4 + 0][r0] = av0.x; As[kk * 4 + 1][r0] = av0.y;
        As[kk * 4 + 2][r0] = av0.z; As[kk * 4 + 3][r0] = av0.w;
        As[kk * 4 + 0][r1] = av1.x; As[kk * 4 + 1][r1] = av1.y;
        As[kk * 4 + 2][r1] = av1.z; As[kk * 4 + 3][r1] = av1.w;
        Bs[kk * 4 + 0][r0] = bv0.x; Bs[kk * 4 + 1][r0] = bv0.y;
        Bs[kk * 4 + 2][r0] = bv0.z; Bs[kk * 4 + 3][r0] = bv0.w;
        Bs[kk * 4 + 0][r1] = bv1.x; Bs[kk * 4 + 1][r1] = bv1.y;
        Bs[kk * 4 + 2][r1] = bv1.z; Bs[kk * 4 + 3][r1] = bv1.w;
        __syncthreads();

        #pragma unroll
        for (int k = 0; k < 16; k++) {
            float4 aq0 = *(const float4*)&As[k][ty * 8];
            float4 aq1 = *(const float4*)&As[k][ty * 8 + 4];
            float4 bq0 = *(const float4*)&Bs[k][tx * 8];
            float4 bq1 = *(const float4*)&Bs[k][tx * 8 + 4];
            float ar[8] = {aq0.x, aq0.y, aq0.z, aq0.w, aq1.x, aq1.y, aq1.z, aq1.w};
            float br[8] = {bq0.x, bq0.y, bq0.z, bq0.w, bq1.x, bq1.y, bq1.z, bq1.w};
            #pragma unroll
            for (int i = 0; i < 8; i++)
                #pragma unroll
                for (int j = 0; j < 8; j++)
                    acc[i][j] = fmaf(ar[i], br[j], acc[i][j]);
        }
        __syncthreads();
    }

    const int ncol = tileN + tx * 8;
    float4 bb0 = *(const float4*)(bias + ncol);
    float4 bb1 = *(const float4*)(bias + ncol + 4);
    #pragma unroll
    for (int i = 0; i < 8; i++) {
        int m = tileM + ty * 8 + i;
        if (m >= M) continue;
        int cr = scatter ? scatter[m] : m;
        float* crow = C + (size_t)cr * ldc + ncol;
        float4 o0, o1;
        o0.x = acc[i][0] + bb0.x; o0.y = acc[i][1] + bb0.y;
        o0.z = acc[i][2] + bb0.z; o0.w = acc[i][3] + bb0.w;
        o1.x = acc[i][4] + bb1.x; o1.y = acc[i][5] + bb1.y;
        o1.z = acc[i][6] + bb1.z; o1.w = acc[i][7] + bb1.w;
        if (relu) {
            o0.x = fmaxf(o0.x, 0.f); o0.y = fmaxf(o0.y, 0.f);
            o0.z = fmaxf(o0.z, 0.f); o0.w = fmaxf(o0.w, 0.f);
            o1.x = fmaxf(o1.x, 0.f); o1.y = fmaxf(o1.y, 0.f);
            o1.z = fmaxf(o1.z, 0.f); o1.w = fmaxf(o1.w, 0.f);
        }
        *(float4*)(crow)     = o0;
        *(float4*)(crow + 4) = o1;
    }
}

// ---------------------------------------------------------------------------
// tf32 tensor-core NT GEMM for the branch chains.
// C[m,n] = sum_k A[row(m),k] * W[n,k] + bias[n]
// Tile: 128x128, BK=32, 8 warps (2Mx4N), warp tile 64x32 via mma.m16n8k8.tf32.
// Dynamic M (*cntp), optional gather on A rows, optional scatter on C rows.
// ---------------------------------------------------------------------------
__device__ __forceinline__ float cvt_tf32(float x) {
    unsigned u;
    asm("cvt.rna.tf32.f32 %0, %1;" : "=r"(u) : "f"(x));
    return __uint_as_float(u);
}

__device__ __forceinline__ void mma_tf32(float (&d)[4], const unsigned (&a)[4],
                                         const unsigned (&b)[2]) {
    asm volatile(
        "mma.sync.aligned.m16n8k8.row.col.f32.tf32.tf32.f32 "
        "{%0,%1,%2,%3}, {%4,%5,%6,%7}, {%8,%9}, {%0,%1,%2,%3};\n"
        : "+f"(d[0]), "+f"(d[1]), "+f"(d[2]), "+f"(d[3])
        : "r"(a[0]), "r"(a[1]), "r"(a[2]), "r"(a[3]), "r"(b[0]), "r"(b[1]));
}

#define TC_PAD 8   // ldm = 136 words -> conflict-free fragment loads (8c+g spans 0..31)

__global__ __launch_bounds__(256, 2)
void k_gemm_tc(const float* __restrict__ A, const float* __restrict__ W,
               const float* __restrict__ bias, float* __restrict__ C,
               int M, const int* __restrict__ cntp, int K,
               const int* __restrict__ gather, const int* __restrict__ scatter,
               int ldc, int relu)
{
    if (cntp) M = *cntp;
    const int tileM = blockIdx.y * 128;
    if (tileM >= M) return;
    const int tileN = blockIdx.x * 128;

    __shared__ float As[32][128 + TC_PAD];
    __shared__ float Bs[32][128 + TC_PAD];

    const int tid  = threadIdx.x;
    const int lane = tid & 31;
    const int warp = tid >> 5;
    const int warpM = warp >> 2;       // 0..1
    const int warpN = warp & 3;        // 0..3
    const int wm0 = warpM * 64;
    const int wn0 = warpN * 32;
    const int g = lane >> 2;           // 0..7
    const int c = lane & 3;            // 0..3

    // gmem load mapping: thread covers rows rbase+32*i (i=0..3), float4 slot col4
    const int col4  = tid & 7;
    const int kk4   = col4 * 4;
    const int rbase = tid >> 3;        // 0..31

    const float* aptr[4];
    bool avalid[4];
    const float* bptr[4];
    #pragma unroll
    for (int i = 0; i < 4; i++) {
        int r = rbase + 32 * i;
        int m = tileM + r;
        avalid[i] = (m < M);
        int grow = avalid[i] ? (gather ? gather[m] : m) : 0;
        aptr[i] = A + (size_t)grow * K + kk4;
        bptr[i] = W + (size_t)(tileN + r) * K + kk4;
    }

    float acc[4][4][4];
    #pragma unroll
    for (int mt = 0; mt < 4; mt++)
        #pragma unroll
        for (int nt = 0; nt < 4; nt++)
            #pragma unroll
            for (int q = 0; q < 4; q++) acc[mt][nt][q] = 0.f;

    for (int k0 = 0; k0 < K; k0 += 32) {
        #pragma unroll
        for (int i = 0; i < 4; i++) {
            int r = rbase + 32 * i;
            float4 av = avalid[i] ? *(const float4*)(aptr[i] + k0)
                                  : make_float4(0.f, 0.f, 0.f, 0.f);
            float4 bv = *(const float4*)(bptr[i] + k0);
            As[kk4 + 0][r] = cvt_tf32(av.x);
            As[kk4 + 1][r] = cvt_tf32(av.y);
            As[kk4 + 2][r] = cvt_tf32(av.z);
            As[kk4 + 3][r] = cvt_tf32(av.w);
            Bs[kk4 + 0][r] = cvt_tf32(bv.x);
            Bs[kk4 + 1][r] = cvt_tf32(bv.y);
            Bs[kk4 + 2][r] = cvt_tf32(bv.z);
            Bs[kk4 + 3][r] = cvt_tf32(bv.w);
        }
        __syncthreads();

        #pragma unroll
        for (int ks = 0; ks < 4; ks++) {
            const int kb = ks * 8;
            unsigned afr[4][4];
            #pragma unroll
            for (int mt = 0; mt < 4; mt++) {
                int m = wm0 + mt * 16 + g;
                afr[mt][0] = __float_as_uint(As[kb + c][m]);
                afr[mt][1] = __float_as_uint(As[kb + c][m + 8]);
                afr[mt][2] = __float_as_uint(As[kb + c + 4][m]);
                afr[mt][3] = __float_as_uint(As[kb + c + 4][m + 8]);
            }
            unsigned bfr[4][2];
            #pragma unroll
            for (int nt = 0; nt < 4; nt++) {
                int n = wn0 + nt * 8 + g;
                bfr[nt][0] = __float_as_uint(Bs[kb + c][n]);
                bfr[nt][1] = __float_as_uint(Bs[kb + c + 4][n]);
            }
            #pragma unroll
            for (int mt = 0; mt < 4; mt++)
                #pragma unroll
                for (int nt = 0; nt < 4; nt++)
                    mma_tf32(acc[mt][nt], afr[mt], bfr[nt]);
        }
        __syncthreads();
    }

    // Epilogue: bias, optional ReLU, optional row scatter. float2 stores.
    #pragma unroll
    for (int mt = 0; mt < 4; mt++) {
        int rowA = tileM + wm0 + mt * 16 + g;
        #pragma unroll
        for (int h = 0; h < 2; h++) {
            int r = rowA + 8 * h;
            if (r >= M) continue;
            int cr = scatter ? scatter[r] : r;
            float* crow = C + (size_t)cr * ldc;
            #pragma unroll
            for (int nt = 0; nt < 4; nt++) {
                int col = tileN + wn0 + nt * 8 + c * 2;
                float2 bb = *(const float2*)(bias + col);
                float2 o;
                o.x = acc[mt][nt][2 * h + 0] + bb.x;
                o.y = acc[mt][nt][2 * h + 1] + bb.y;
                if (relu) { o.x = fmaxf(o.x, 0.f); o.y = fmaxf(o.y, 0.f); }
                *(float2*)(crow + col) = o;
            }
        }
    }
}

// ---------------------------------------------------------------------------
extern "C" void kernel_launch(void* const* d_in, const int* in_sizes, int n_in,
                              void* d_out, int out_size)
{
    const float* h       = (const float*)d_in[0];   // [4,4096,2048]
    const float* freq    = (const float*)d_in[1];   // [4,4096]
    const float* imp     = (const float*)d_in[2];   // [4,4096]
    const float* comp1_W = (const float*)d_in[3];   // [1024,2048]
    const float* comp1_b = (const float*)d_in[4];
    const float* adpt1_W = (const float*)d_in[5];   // [1024,1024]
    const float* adpt1_b = (const float*)d_in[6];
    const float* dec1_W  = (const float*)d_in[7];   // [2048,1024]
    const float* dec1_b  = (const float*)d_in[8];
    const float* comp2_W = (const float*)d_in[9];   // [512,2048]
    const float* comp2_b = (const float*)d_in[10];
    const float* adpt2_W = (const float*)d_in[11];  // [512,512]
    const float* adpt2_b = (const float*)d_in[12];
    const float* dec2_W  = (const float*)d_in[13];  // [2048,512]
    const float* dec2_b  = (const float*)d_in[14];
    const float* sel1_W  = (const float*)d_in[15];  // [512,2048]
    const float* sel1_b  = (const float*)d_in[16];
    const float* sel2_W  = (const float*)d_in[17];  // [3,512]
    const float* sel2_b  = (const float*)d_in[18];
    float* out = (float*)d_out;

    float *bufA, *bufB; int *idx1, *idx2, *cnt;
    cudaGetSymbolAddress((void**)&bufA, g_bufA);
    cudaGetSymbolAddress((void**)&bufB, g_bufB);
    cudaGetSymbolAddress((void**)&idx1, g_idx1);
    cudaGetSymbolAddress((void**)&idx2, g_idx2);
    cudaGetSymbolAddress((void**)&cnt,  g_cnt);

    const int MAXY = TOK / 128;  // 128 m-tiles

    k_init_counters<<<1, 32>>>();

    // out = h (covers selected==0; branches overwrite their rows)
    {
        int n4 = TOK * HDIM / 4;
        k_copy4<<<(n4 + 255) / 256, 256>>>(h, out, n4);
    }

    // selector hidden (fp32 SIMT -- keeps argmax decisions exact): bufA [TOK,512]
    k_gemm128<<<dim3(512 / 128, MAXY), 256>>>(h, sel1_W, sel1_b, bufA,
        TOK, nullptr, HDIM, nullptr, nullptr, 512, freq, imp, 1);

    // logits + argmax + index compaction
    k_argmax_compact<<<(TOK * 32 + 255) / 256, 256>>>(bufA, sel2_W, sel2_b);

    // ---- branch 1 (tokens with selected==1), compacted, tf32 tensor cores ----
    k_gemm_tc<<<dim3(1024 / 128, MAXY), 256>>>(h, comp1_W, comp1_b, bufB,
        TOK, &cnt[0], HDIM, idx1, nullptr, 1024, 0);
    k_gemm_tc<<<dim3(1024 / 128, MAXY), 256>>>(bufB, adpt1_W, adpt1_b, bufA,
        TOK, &cnt[0], 1024, nullptr, nullptr, 1024, 0);
    k_gemm_tc<<<dim3(2048 / 128, MAXY), 256>>>(bufA, dec1_W, dec1_b, out,
        TOK, &cnt[0], 1024, nullptr, idx1, HDIM, 0);

    // ---- branch 2 (tokens with selected==2), compacted, tf32 tensor cores ----
    k_gemm_tc<<<dim3(512 / 128, MAXY), 256>>>(h, comp2_W, comp2_b, bufB,
        TOK, &cnt[1], HDIM, idx2, nullptr, 512, 0);
    k_gemm_tc<<<dim3(512 / 128, MAXY), 256>>>(bufB, adpt2_W, adpt2_b, bufA,
        TOK, &cnt[1], 512, nullptr, nullptr, 512, 0);
    k_gemm_tc<<<dim3(2048 / 128, MAXY), 256>>>(bufA, dec2_W, dec2_b, out,
        TOK, &cnt[1], 512, nullptr, idx2, HDIM, 0);
}

// round 4
// speedup vs baseline: 1.9557x; 1.2825x over previous
#include <cuda_runtime.h>

// Problem constants (fixed shapes from reference)
#define TOK   (4 * 4096)   // B*S = 16384 tokens
#define HDIM  2048
#define TAU   0.02f        // argmax-gap threshold for exact fp32 recheck

// Scratch
__device__ float g_bufM[(size_t)TOK * HDIM];  // 128 MB: modulated h for selector
__device__ float g_bufA[(size_t)TOK * 1024];  // 64 MB
__device__ float g_bufB[(size_t)TOK * 1024];  // 64 MB
__device__ int   g_idx1[TOK];
__device__ int   g_idx2[TOK];
__device__ int   g_idxR[TOK];
__device__ int   g_sel[TOK];
__device__ int   g_cnt[3];   // [0]=branch1, [1]=branch2, [2]=recheck

// ---------------------------------------------------------------------------
__global__ void k_init_counters() {
    g_cnt[0] = 0; g_cnt[1] = 0; g_cnt[2] = 0;
}

// One pass over h: out = h (default for selected==0) AND bufM = modulated h.
__global__ void k_prep(const float* __restrict__ h, float* __restrict__ out,
                       float* __restrict__ bufM,
                       const float* __restrict__ freq, const float* __restrict__ imp) {
    int i = blockIdx.x * blockDim.x + threadIdx.x;     // float4 index
    if (i >= TOK * (HDIM / 4)) return;
    float4 v = ((const float4*)h)[i];
    ((float4*)out)[i] = v;
    int tok = i >> 9;                 // / (HDIM/4)
    int col = (i & 511) << 2;
    float s = (col < HDIM / 2) ? freq[tok] : imp[tok];
    v.x *= s; v.y *= s; v.z *= s; v.w *= s;
    ((float4*)bufM)[i] = v;
}

// ---------------------------------------------------------------------------
// Selector decision from (approximate) hid. Writes g_sel; near-ties go to the
// recheck list. One warp per token.
__global__ void k_sel_fast(const float* __restrict__ hid,   // [TOK,512]
                           const float* __restrict__ W2,    // [3,512]
                           const float* __restrict__ b2) {
    int t = blockIdx.x * blockDim.x + threadIdx.x;
    int tok = t >> 5, lane = t & 31;
    if (tok >= TOK) return;
    const float* hrow = hid + (size_t)tok * 512;
    float s0 = 0.f, s1 = 0.f, s2 = 0.f;
    #pragma unroll 4
    for (int k = lane; k < 512; k += 32) {
        float v = hrow[k];
        s0 += v * W2[k];
        s1 += v * W2[512 + k];
        s2 += v * W2[1024 + k];
    }
    #pragma unroll
    for (int o = 16; o; o >>= 1) {
        s0 += __shfl_down_sync(0xffffffffu, s0, o);
        s1 += __shfl_down_sync(0xffffffffu, s1, o);
        s2 += __shfl_down_sync(0xffffffffu, s2, o);
    }
    if (lane == 0) {
        s0 += b2[0]; s1 += b2[1]; s2 += b2[2];
        int sel = 0; float best = s0;             // first-max rule: strict '>'
        if (s1 > best) { best = s1; sel = 1; }
        if (s2 > best) { best = s2; sel = 2; }
        g_sel[tok] = sel;
        float m1 = fmaxf(s0, fmaxf(s1, s2));
        float mn = fminf(s0, fminf(s1, s2));
        float m2 = s0 + s1 + s2 - m1 - mn;        // second largest
        if (m1 - m2 < TAU) {
            int p = atomicAdd(&g_cnt[2], 1);
            g_idxR[p] = tok;
        }
    }
}

// Final decision for rechecked tokens from exact fp32 hid rows (compacted).
__global__ void k_sel_fix(const float* __restrict__ hidx,   // [nR,512] exact
                          const float* __restrict__ W2,
                          const float* __restrict__ b2) {
    int t = blockIdx.x * blockDim.x + threadIdx.x;
    int r = t >> 5, lane = t & 31;
    if (r >= g_cnt[2]) return;
    const float* hrow = hidx + (size_t)r * 512;
    float s0 = 0.f, s1 = 0.f, s2 = 0.f;
    #pragma unroll 4
    for (int k = lane; k < 512; k += 32) {
        float v = hrow[k];
        s0 += v * W2[k];
        s1 += v * W2[512 + k];
        s2 += v * W2[1024 + k];
    }
    #pragma unroll
    for (int o = 16; o; o >>= 1) {
        s0 += __shfl_down_sync(0xffffffffu, s0, o);
        s1 += __shfl_down_sync(0xffffffffu, s1, o);
        s2 += __shfl_down_sync(0xffffffffu, s2, o);
    }
    if (lane == 0) {
        s0 += b2[0]; s1 += b2[1]; s2 += b2[2];
        int sel = 0; float best = s0;
        if (s1 > best) { best = s1; sel = 1; }
        if (s2 > best) { best = s2; sel = 2; }
        g_sel[g_idxR[r]] = sel;
    }
}

// Build branch index lists from final g_sel.
__global__ void k_compact() {
    int tok = blockIdx.x * blockDim.x + threadIdx.x;
    if (tok >= TOK) return;
    int s = g_sel[tok];
    if (s == 1)      { int p = atomicAdd(&g_cnt[0], 1); g_idx1[p] = tok; }
    else if (s == 2) { int p = atomicAdd(&g_cnt[1], 1); g_idx2[p] = tok; }
}

// ---------------------------------------------------------------------------
// fp32 SIMT NT GEMM — used only for the exact recheck (argmax must stay exact)
// ---------------------------------------------------------------------------
__global__ __launch_bounds__(256, 2)
void k_gemm128(const float* __restrict__ A, const float* __restrict__ W,
               const float* __restrict__ bias, float* __restrict__ C,
               int M, const int* __restrict__ cntp, int K,
               const int* __restrict__ gather, const int* __restrict__ scatter,
               int ldc,
               const float* __restrict__ freq, const float* __restrict__ imp,
               int relu)
{
    if (cntp) M = *cntp;
    const int tileM = blockIdx.y * 128;
    if (tileM >= M) return;
    const int tileN = blockIdx.x * 128;

    __shared__ float As[16][128];
    __shared__ float Bs[16][128];

    const int tid = threadIdx.x;
    const int tx = tid & 15;
    const int ty = tid >> 4;

    const int kk = tid & 3;
    const int r0 = tid >> 2;
    const int r1 = r0 + 64;

    const int m0 = tileM + r0;
    const int m1 = tileM + r1;
    const bool v0 = (m0 < M);
    const bool v1 = (m1 < M);
    const int gr0 = v0 ? (gather ? gather[m0] : m0) : 0;
    const int gr1 = v1 ? (gather ? gather[m1] : m1) : 0;
    const float* a0p = A + (size_t)gr0 * K;
    const float* a1p = A + (size_t)gr1 * K;
    float fr0 = 1.f, im0 = 1.f, fr1 = 1.f, im1 = 1.f;
    if (freq) { fr0 = freq[gr0]; im0 = imp[gr0]; fr1 = freq[gr1]; im1 = imp[gr1]; }

    const float* w0p = W + (size_t)(tileN + r0) * K;
    const float* w1p = W + (size_t)(tileN + r1) * K;

    float acc[8][8];
    #pragma unroll
    for (int i = 0; i < 8; i++)
        #pragma unroll
        for (int j = 0; j < 8; j++) acc[i][j] = 0.f;

    const int halfK = K >> 1;

    for (int k0 = 0; k0 < K; k0 += 16) {
        const int kc = k0 + kk * 4;
        float4 av0 = v0 ? *(const float4*)(a0p + kc) : make_float4(0.f, 0.f, 0.f, 0.f);
        float4 av1 = v1 ? *(const float4*)(a1p + kc) : make_float4(0.f, 0.f, 0.f, 0.f);
        if (freq) {
            float s0 = (kc < halfK) ? fr0 : im0;
            float s1 = (kc < halfK) ? fr1 : im1;
            av0.x *= s0; av0.y *= s0; av0.z *= s0; av0.w *= s0;
            av1.x *= s1; av1.y *= s1; av1.z *= s1; av1.w *= s1;
        }
        float4 bv0 = *(const float4*)(w0p + kc);
        float4 bv1 = *(const float4*)(w1p + kc);

        As[kk * 4 + 0][r0] = av0.x; As[kk * 4 + 1][r0] = av0.y;
        As[kk * 4 + 2][r0] = av0.z; As[kk * 4 + 3][r0] = av0.w;
        As[kk * 4 + 0][r1] = av1.x; As[kk * 4 + 1][r1] = av1.y;
        As[kk * 4 + 2][r1] = av1.z; As[kk * 4 + 3][r1] = av1.w;
        Bs[kk * 4 + 0][r0] = bv0.x; Bs[kk * 4 + 1][r0] = bv0.y;
        Bs[kk * 4 + 2][r0] = bv0.z; Bs[kk * 4 + 3][r0] = bv0.w;
        Bs[kk * 4 + 0][r1] = bv1.x; Bs[kk * 4 + 1][r1] = bv1.y;
        Bs[kk * 4 + 2][r1] = bv1.z; Bs[kk * 4 + 3][r1] = bv1.w;
        __syncthreads();

        #pragma unroll
        for (int k = 0; k < 16; k++) {
            float4 aq0 = *(const float4*)&As[k][ty * 8];
            float4 aq1 = *(const float4*)&As[k][ty * 8 + 4];
            float4 bq0 = *(const float4*)&Bs[k][tx * 8];
            float4 bq1 = *(const float4*)&Bs[k][tx * 8 + 4];
            float ar[8] = {aq0.x, aq0.y, aq0.z, aq0.w, aq1.x, aq1.y, aq1.z, aq1.w};
            float br[8] = {bq0.x, bq0.y, bq0.z, bq0.w, bq1.x, bq1.y, bq1.z, bq1.w};
            #pragma unroll
            for (int i = 0; i < 8; i++)
                #pragma unroll
                for (int j = 0; j < 8; j++)
                    acc[i][j] = fmaf(ar[i], br[j], acc[i][j]);
        }
        __syncthreads();
    }

    const int ncol = tileN + tx * 8;
    float4 bb0 = *(const float4*)(bias + ncol);
    float4 bb1 = *(const float4*)(bias + ncol + 4);
    #pragma unroll
    for (int i = 0; i < 8; i++) {
        int m = tileM + ty * 8 + i;
        if (m >= M) continue;
        int cr = scatter ? scatter[m] : m;
        float* crow = C + (size_t)cr * ldc + ncol;
        float4 o0, o1;
        o0.x = acc[i][0] + bb0.x; o0.y = acc[i][1] + bb0.y;
        o0.z = acc[i][2] + bb0.z; o0.w = acc[i][3] + bb0.w;
        o1.x = acc[i][4] + bb1.x; o1.y = acc[i][5] + bb1.y;
        o1.z = acc[i][6] + bb1.z; o1.w = acc[i][7] + bb1.w;
        if (relu) {
            o0.x = fmaxf(o0.x, 0.f); o0.y = fmaxf(o0.y, 0.f);
            o0.z = fmaxf(o0.z, 0.f); o0.w = fmaxf(o0.w, 0.f);
            o1.x = fmaxf(o1.x, 0.f); o1.y = fmaxf(o1.y, 0.f);
            o1.z = fmaxf(o1.z, 0.f); o1.w = fmaxf(o1.w, 0.f);
        }
        *(float4*)(crow)     = o0;
        *(float4*)(crow + 4) = o1;
    }
}

// ---------------------------------------------------------------------------
// tf32 tensor-core NT GEMM, software-pipelined (register prefetch of next
// K-slice overlaps gmem latency with the mma phase).
// Tile: 128x128, BK=16, 8 warps (2Mx4N), warp tile 64x32, mma.m16n8k8.tf32.
// ---------------------------------------------------------------------------
__device__ __forceinline__ float cvt_tf32(float x) {
    unsigned u;
    asm("cvt.rna.tf32.f32 %0, %1;" : "=r"(u) : "f"(x));
    return __uint_as_float(u);
}

__device__ __forceinline__ void mma_tf32(float (&d)[4], const unsigned (&a)[4],
                                         const unsigned (&b)[2]) {
    asm volatile(
        "mma.sync.aligned.m16n8k8.row.col.f32.tf32.tf32.f32 "
        "{%0,%1,%2,%3}, {%4,%5,%6,%7}, {%8,%9}, {%0,%1,%2,%3};\n"
        : "+f"(d[0]), "+f"(d[1]), "+f"(d[2]), "+f"(d[3])
        : "r"(a[0]), "r"(a[1]), "r"(a[2]), "r"(a[3]), "r"(b[0]), "r"(b[1]));
}

#define TC_PAD 8   // ldm = 136 words -> conflict-free fragment loads

__global__ __launch_bounds__(256, 2)
void k_gemm_tc(const float* __restrict__ A, const float* __restrict__ W,
               const float* __restrict__ bias, float* __restrict__ C,
               int M, const int* __restrict__ cntp, int K,
               const int* __restrict__ gather, const int* __restrict__ scatter,
               int ldc, int relu)
{
    if (cntp) M = *cntp;
    const int tileM = blockIdx.y * 128;
    if (tileM >= M) return;
    const int tileN = blockIdx.x * 128;

    __shared__ float As[16][128 + TC_PAD];
    __shared__ float Bs[16][128 + TC_PAD];

    const int tid  = threadIdx.x;
    const int lane = tid & 31;
    const int warp = tid >> 5;
    const int warpM = warp >> 2;       // 0..1
    const int warpN = warp & 3;        // 0..3
    const int wm0 = warpM * 64;
    const int wn0 = warpN * 32;
    const int g = lane >> 2;           // 0..7
    const int c = lane & 3;            // 0..3

    // gmem loader mapping: 2 float4 per array per thread (BK=16)
    const int kk  = tid & 3;
    const int kk4 = kk * 4;
    const int r0  = tid >> 2;          // 0..63
    const int r1  = r0 + 64;

    const int m0 = tileM + r0;
    const int m1 = tileM + r1;
    const bool v0 = (m0 < M);
    const bool v1 = (m1 < M);
    const int gr0 = v0 ? (gather ? gather[m0] : m0) : 0;
    const int gr1 = v1 ? (gather ? gather[m1] : m1) : 0;
    const float* a0p = A + (size_t)gr0 * K + kk4;
    const float* a1p = A + (size_t)gr1 * K + kk4;
    const float* w0p = W + (size_t)(tileN + r0) * K + kk4;
    const float* w1p = W + (size_t)(tileN + r1) * K + kk4;

    float acc[4][4][4];
    #pragma unroll
    for (int mt = 0; mt < 4; mt++)
        #pragma unroll
        for (int nt = 0; nt < 4; nt++)
            #pragma unroll
            for (int q = 0; q < 4; q++) acc[mt][nt][q] = 0.f;

    const float4 zero4 = make_float4(0.f, 0.f, 0.f, 0.f);
    float4 av0 = v0 ? *(const float4*)(a0p) : zero4;
    float4 av1 = v1 ? *(const float4*)(a1p) : zero4;
    float4 bv0 = *(const float4*)(w0p);
    float4 bv1 = *(const float4*)(w1p);

    for (int k0 = 0; k0 < K; k0 += 16) {
        As[kk4 + 0][r0] = cvt_tf32(av0.x); As[kk4 + 1][r0] = cvt_tf32(av0.y);
        As[kk4 + 2][r0] = cvt_tf32(av0.z); As[kk4 + 3][r0] = cvt_tf32(av0.w);
        As[kk4 + 0][r1] = cvt_tf32(av1.x); As[kk4 + 1][r1] = cvt_tf32(av1.y);
        As[kk4 + 2][r1] = cvt_tf32(av1.z); As[kk4 + 3][r1] = cvt_tf32(av1.w);
        Bs[kk4 + 0][r0] = cvt_tf32(bv0.x); Bs[kk4 + 1][r0] = cvt_tf32(bv0.y);
        Bs[kk4 + 2][r0] = cvt_tf32(bv0.z); Bs[kk4 + 3][r0] = cvt_tf32(bv0.w);
        Bs[kk4 + 0][r1] = cvt_tf32(bv1.x); Bs[kk4 + 1][r1] = cvt_tf32(bv1.y);
        Bs[kk4 + 2][r1] = cvt_tf32(bv1.z); Bs[kk4 + 3][r1] = cvt_tf32(bv1.w);
        __syncthreads();

        // Prefetch next slice: latency hidden behind the mma phase below.
        const int kn = k0 + 16;
        if (kn < K) {
            av0 = v0 ? *(const float4*)(a0p + kn) : zero4;
            av1 = v1 ? *(const float4*)(a1p + kn) : zero4;
            bv0 = *(const float4*)(w0p + kn);
            bv1 = *(const float4*)(w1p + kn);
        }

        #pragma unroll
        for (int ks = 0; ks < 2; ks++) {
            const int kb = ks * 8;
            unsigned afr[4][4];
            #pragma unroll
            for (int mt = 0; mt < 4; mt++) {
                int m = wm0 + mt * 16 + g;
                afr[mt][0] = __float_as_uint(As[kb + c][m]);
                afr[mt][1] = __float_as_uint(As[kb + c][m + 8]);
                afr[mt][2] = __float_as_uint(As[kb + c + 4][m]);
                afr[mt][3] = __float_as_uint(As[kb + c + 4][m + 8]);
            }
            unsigned bfr[4][2];
            #pragma unroll
            for (int nt = 0; nt < 4; nt++) {
                int n = wn0 + nt * 8 + g;
                bfr[nt][0] = __float_as_uint(Bs[kb + c][n]);
                bfr[nt][1] = __float_as_uint(Bs[kb + c + 4][n]);
            }
            #pragma unroll
            for (int mt = 0; mt < 4; mt++)
                #pragma unroll
                for (int nt = 0; nt < 4; nt++)
                    mma_tf32(acc[mt][nt], afr[mt], bfr[nt]);
        }
        __syncthreads();
    }

    // Epilogue: bias, optional ReLU, optional row scatter. float2 stores.
    #pragma unroll
    for (int mt = 0; mt < 4; mt++) {
        int rowA = tileM + wm0 + mt * 16 + g;
        #pragma unroll
        for (int h2 = 0; h2 < 2; h2++) {
            int r = rowA + 8 * h2;
            if (r >= M) continue;
            int cr = scatter ? scatter[r] : r;
            float* crow = C + (size_t)cr * ldc;
            #pragma unroll
            for (int nt = 0; nt < 4; nt++) {
                int col = tileN + wn0 + nt * 8 + c * 2;
                float2 bb = *(const float2*)(bias + col);
                float2 o;
                o.x = acc[mt][nt][2 * h2 + 0] + bb.x;
                o.y = acc[mt][nt][2 * h2 + 1] + bb.y;
                if (relu) { o.x = fmaxf(o.x, 0.f); o.y = fmaxf(o.y, 0.f); }
                *(float2*)(crow + col) = o;
            }
        }
    }
}

// ---------------------------------------------------------------------------
extern "C" void kernel_launch(void* const* d_in, const int* in_sizes, int n_in,
                              void* d_out, int out_size)
{
    const float* h       = (const float*)d_in[0];   // [4,4096,2048]
    const float* freq    = (const float*)d_in[1];   // [4,4096]
    const float* imp     = (const float*)d_in[2];   // [4,4096]
    const float* comp1_W = (const float*)d_in[3];   // [1024,2048]
    const float* comp1_b = (const float*)d_in[4];
    const float* adpt1_W = (const float*)d_in[5];   // [1024,1024]
    const float* adpt1_b = (const float*)d_in[6];
    const float* dec1_W  = (const float*)d_in[7];   // [2048,1024]
    const float* dec1_b  = (const float*)d_in[8];
    const float* comp2_W = (const float*)d_in[9];   // [512,2048]
    const float* comp2_b = (const float*)d_in[10];
    const float* adpt2_W = (const float*)d_in[11];  // [512,512]
    const float* adpt2_b = (const float*)d_in[12];
    const float* dec2_W  = (const float*)d_in[13];  // [2048,512]
    const float* dec2_b  = (const float*)d_in[14];
    const float* sel1_W  = (const float*)d_in[15];  // [512,2048]
    const float* sel1_b  = (const float*)d_in[16];
    const float* sel2_W  = (const float*)d_in[17];  // [3,512]
    const float* sel2_b  = (const float*)d_in[18];
    float* out = (float*)d_out;

    float *bufM, *bufA, *bufB; int *idx1, *idx2, *idxR, *cnt;
    cudaGetSymbolAddress((void**)&bufM, g_bufM);
    cudaGetSymbolAddress((void**)&bufA, g_bufA);
    cudaGetSymbolAddress((void**)&bufB, g_bufB);
    cudaGetSymbolAddress((void**)&idx1, g_idx1);
    cudaGetSymbolAddress((void**)&idx2, g_idx2);
    cudaGetSymbolAddress((void**)&idxR, g_idxR);
    cudaGetSymbolAddress((void**)&cnt,  g_cnt);

    const int MAXY = TOK / 128;  // 128 m-tiles

    k_init_counters<<<1, 32>>>();

    // out = h AND bufM = modulated h, one pass
    {
        int n4 = TOK * HDIM / 4;
        k_prep<<<(n4 + 255) / 256, 256>>>(h, out, bufM, freq, imp);
    }

    // selector hidden on tensor cores (tf32): bufA [TOK,512]
    k_gemm_tc<<<dim3(512 / 128, MAXY), 256>>>(bufM, sel1_W, sel1_b, bufA,
        TOK, nullptr, HDIM, nullptr, nullptr, 512, 1);

    // fast argmax + near-tie flagging
    k_sel_fast<<<(TOK * 32 + 255) / 256, 256>>>(bufA, sel2_W, sel2_b);

    // exact fp32 hid for flagged tokens (gathered, modulated) -> bufB [nR,512]
    k_gemm128<<<dim3(512 / 128, MAXY), 256>>>(h, sel1_W, sel1_b, bufB,
        TOK, &cnt[2], HDIM, idxR, nullptr, 512, freq, imp, 1);
    k_sel_fix<<<(TOK * 32 + 255) / 256, 256>>>(bufB, sel2_W, sel2_b);

    // build branch index lists from final decisions
    k_compact<<<(TOK + 255) / 256, 256>>>();

    // ---- branch 1 (selected==1), compacted, pipelined tf32 tensor cores ----
    k_gemm_tc<<<dim3(1024 / 128, MAXY), 256>>>(h, comp1_W, comp1_b, bufB,
        TOK, &cnt[0], HDIM, idx1, nullptr, 1024, 0);
    k_gemm_tc<<<dim3(1024 / 128, MAXY), 256>>>(bufB, adpt1_W, adpt1_b, bufA,
        TOK, &cnt[0], 1024, nullptr, nullptr, 1024, 0);
    k_gemm_tc<<<dim3(2048 / 128, MAXY), 256>>>(bufA, dec1_W, dec1_b, out,
        TOK, &cnt[0], 1024, nullptr, idx1, HDIM, 0);

    // ---- branch 2 (selected==2), compacted, pipelined tf32 tensor cores ----
    k_gemm_tc<<<dim3(512 / 128, MAXY), 256>>>(h, comp2_W, comp2_b, bufB,
        TOK, &cnt[1], HDIM, idx2, nullptr, 512, 0);
    k_gemm_tc<<<dim3(512 / 128, MAXY), 256>>>(bufB, adpt2_W, adpt2_b, bufA,
        TOK, &cnt[1], 512, nullptr, nullptr, 512, 0);
    k_gemm_tc<<<dim3(2048 / 128, MAXY), 256>>>(bufA, dec2_W, dec2_b, out,
        TOK, &cnt[1], 512, nullptr, idx2, HDIM, 0);
}

// round 5
// speedup vs baseline: 3.1849x; 1.6285x over previous
#include <cuda_runtime.h>

// Problem constants (fixed shapes from reference)
#define TOK   (4 * 4096)   // B*S = 16384 tokens
#define HDIM  2048
#define TAU   0.02f        // argmax-gap threshold for exact fp32 recheck

// Scratch
__device__ float g_bufM[(size_t)TOK * HDIM];  // 128 MB: modulated h for selector
__device__ float g_bufA[(size_t)TOK * 1024];  // 64 MB
__device__ float g_bufB[(size_t)TOK * 1024];  // 64 MB
__device__ int   g_idx1[TOK];
__device__ int   g_idx2[TOK];
__device__ int   g_idxR[TOK];
__device__ int   g_sel[TOK];
__device__ int   g_cnt[3];   // [0]=branch1, [1]=branch2, [2]=recheck

// ---------------------------------------------------------------------------
__global__ void k_init_counters() {
    g_cnt[0] = 0; g_cnt[1] = 0; g_cnt[2] = 0;
}

// One pass over h: out = h (default for selected==0) AND bufM = modulated h.
__global__ void k_prep(const float* __restrict__ h, float* __restrict__ out,
                       float* __restrict__ bufM,
                       const float* __restrict__ freq, const float* __restrict__ imp) {
    int i = blockIdx.x * blockDim.x + threadIdx.x;     // float4 index
    if (i >= TOK * (HDIM / 4)) return;
    float4 v = ((const float4*)h)[i];
    ((float4*)out)[i] = v;
    int tok = i >> 9;                 // / (HDIM/4)
    int col = (i & 511) << 2;
    float s = (col < HDIM / 2) ? freq[tok] : imp[tok];
    v.x *= s; v.y *= s; v.z *= s; v.w *= s;
    ((float4*)bufM)[i] = v;
}

// ---------------------------------------------------------------------------
// Selector decision from (approximate) hid. Near-ties go to the recheck list.
__global__ void k_sel_fast(const float* __restrict__ hid,   // [TOK,512]
                           const float* __restrict__ W2,    // [3,512]
                           const float* __restrict__ b2) {
    int t = blockIdx.x * blockDim.x + threadIdx.x;
    int tok = t >> 5, lane = t & 31;
    if (tok >= TOK) return;
    const float* hrow = hid + (size_t)tok * 512;
    float s0 = 0.f, s1 = 0.f, s2 = 0.f;
    #pragma unroll 4
    for (int k = lane; k < 512; k += 32) {
        float v = hrow[k];
        s0 += v * W2[k];
        s1 += v * W2[512 + k];
        s2 += v * W2[1024 + k];
    }
    #pragma unroll
    for (int o = 16; o; o >>= 1) {
        s0 += __shfl_down_sync(0xffffffffu, s0, o);
        s1 += __shfl_down_sync(0xffffffffu, s1, o);
        s2 += __shfl_down_sync(0xffffffffu, s2, o);
    }
    if (lane == 0) {
        s0 += b2[0]; s1 += b2[1]; s2 += b2[2];
        int sel = 0; float best = s0;             // first-max rule: strict '>'
        if (s1 > best) { best = s1; sel = 1; }
        if (s2 > best) { best = s2; sel = 2; }
        g_sel[tok] = sel;
        float m1 = fmaxf(s0, fmaxf(s1, s2));
        float mn = fminf(s0, fminf(s1, s2));
        float m2 = s0 + s1 + s2 - m1 - mn;        // second largest
        if (m1 - m2 < TAU) {
            int p = atomicAdd(&g_cnt[2], 1);
            g_idxR[p] = tok;
        }
    }
}

// Final decision for rechecked tokens from exact fp32 hid rows (compacted).
__global__ void k_sel_fix(const float* __restrict__ hidx,   // [nR,512] exact
                          const float* __restrict__ W2,
                          const float* __restrict__ b2) {
    int t = blockIdx.x * blockDim.x + threadIdx.x;
    int r = t >> 5, lane = t & 31;
    if (r >= g_cnt[2]) return;
    const float* hrow = hidx + (size_t)r * 512;
    float s0 = 0.f, s1 = 0.f, s2 = 0.f;
    #pragma unroll 4
    for (int k = lane; k < 512; k += 32) {
        float v = hrow[k];
        s0 += v * W2[k];
        s1 += v * W2[512 + k];
        s2 += v * W2[1024 + k];
    }
    #pragma unroll
    for (int o = 16; o; o >>= 1) {
        s0 += __shfl_down_sync(0xffffffffu, s0, o);
        s1 += __shfl_down_sync(0xffffffffu, s1, o);
        s2 += __shfl_down_sync(0xffffffffu, s2, o);
    }
    if (lane == 0) {
        s0 += b2[0]; s1 += b2[1]; s2 += b2[2];
        int sel = 0; float best = s0;
        if (s1 > best) { best = s1; sel = 1; }
        if (s2 > best) { best = s2; sel = 2; }
        g_sel[g_idxR[r]] = sel;
    }
}

// Build branch index lists from final g_sel.
__global__ void k_compact() {
    int tok = blockIdx.x * blockDim.x + threadIdx.x;
    if (tok >= TOK) return;
    int s = g_sel[tok];
    if (s == 1)      { int p = atomicAdd(&g_cnt[0], 1); g_idx1[p] = tok; }
    else if (s == 2) { int p = atomicAdd(&g_cnt[1], 1); g_idx2[p] = tok; }
}

// ---------------------------------------------------------------------------
// fp32 SIMT NT GEMM — used only for the exact recheck (argmax must stay exact)
// ---------------------------------------------------------------------------
__global__ __launch_bounds__(256, 2)
void k_gemm128(const float* __restrict__ A, const float* __restrict__ W,
               const float* __restrict__ bias, float* __restrict__ C,
               int M, const int* __restrict__ cntp, int K,
               const int* __restrict__ gather, const int* __restrict__ scatter,
               int ldc,
               const float* __restrict__ freq, const float* __restrict__ imp,
               int relu)
{
    if (cntp) M = *cntp;
    const int tileM = blockIdx.y * 128;
    if (tileM >= M) return;
    const int tileN = blockIdx.x * 128;

    __shared__ float As[16][128];
    __shared__ float Bs[16][128];

    const int tid = threadIdx.x;
    const int tx = tid & 15;
    const int ty = tid >> 4;

    const int kk = tid & 3;
    const int r0 = tid >> 2;
    const int r1 = r0 + 64;

    const int m0 = tileM + r0;
    const int m1 = tileM + r1;
    const bool v0 = (m0 < M);
    const bool v1 = (m1 < M);
    const int gr0 = v0 ? (gather ? gather[m0] : m0) : 0;
    const int gr1 = v1 ? (gather ? gather[m1] : m1) : 0;
    const float* a0p = A + (size_t)gr0 * K;
    const float* a1p = A + (size_t)gr1 * K;
    float fr0 = 1.f, im0 = 1.f, fr1 = 1.f, im1 = 1.f;
    if (freq) { fr0 = freq[gr0]; im0 = imp[gr0]; fr1 = freq[gr1]; im1 = imp[gr1]; }

    const float* w0p = W + (size_t)(tileN + r0) * K;
    const float* w1p = W + (size_t)(tileN + r1) * K;

    float acc[8][8];
    #pragma unroll
    for (int i = 0; i < 8; i++)
        #pragma unroll
        for (int j = 0; j < 8; j++) acc[i][j] = 0.f;

    const int halfK = K >> 1;

    for (int k0 = 0; k0 < K; k0 += 16) {
        const int kc = k0 + kk * 4;
        float4 av0 = v0 ? *(const float4*)(a0p + kc) : make_float4(0.f, 0.f, 0.f, 0.f);
        float4 av1 = v1 ? *(const float4*)(a1p + kc) : make_float4(0.f, 0.f, 0.f, 0.f);
        if (freq) {
            float s0 = (kc < halfK) ? fr0 : im0;
            float s1 = (kc < halfK) ? fr1 : im1;
            av0.x *= s0; av0.y *= s0; av0.z *= s0; av0.w *= s0;
            av1.x *= s1; av1.y *= s1; av1.z *= s1; av1.w *= s1;
        }
        float4 bv0 = *(const float4*)(w0p + kc);
        float4 bv1 = *(const float4*)(w1p + kc);

        As[kk * 4 + 0][r0] = av0.x; As[kk * 4 + 1][r0] = av0.y;
        As[kk * 4 + 2][r0] = av0.z; As[kk * 4 + 3][r0] = av0.w;
        As[kk * 4 + 0][r1] = av1.x; As[kk * 4 + 1][r1] = av1.y;
        As[kk * 4 + 2][r1] = av1.z; As[kk * 4 + 3][r1] = av1.w;
        Bs[kk * 4 + 0][r0] = bv0.x; Bs[kk * 4 + 1][r0] = bv0.y;
        Bs[kk * 4 + 2][r0] = bv0.z; Bs[kk * 4 + 3][r0] = bv0.w;
        Bs[kk * 4 + 0][r1] = bv1.x; Bs[kk * 4 + 1][r1] = bv1.y;
        Bs[kk * 4 + 2][r1] = bv1.z; Bs[kk * 4 + 3][r1] = bv1.w;
        __syncthreads();

        #pragma unroll
        for (int k = 0; k < 16; k++) {
            float4 aq0 = *(const float4*)&As[k][ty * 8];
            float4 aq1 = *(const float4*)&As[k][ty * 8 + 4];
            float4 bq0 = *(const float4*)&Bs[k][tx * 8];
            float4 bq1 = *(const float4*)&Bs[k][tx * 8 + 4];
            float ar[8] = {aq0.x, aq0.y, aq0.z, aq0.w, aq1.x, aq1.y, aq1.z, aq1.w};
            float br[8] = {bq0.x, bq0.y, bq0.z, bq0.w, bq1.x, bq1.y, bq1.z, bq1.w};
            #pragma unroll
            for (int i = 0; i < 8; i++)
                #pragma unroll
                for (int j = 0; j < 8; j++)
                    acc[i][j] = fmaf(ar[i], br[j], acc[i][j]);
        }
        __syncthreads();
    }

    const int ncol = tileN + tx * 8;
    float4 bb0 = *(const float4*)(bias + ncol);
    float4 bb1 = *(const float4*)(bias + ncol + 4);
    #pragma unroll
    for (int i = 0; i < 8; i++) {
        int m = tileM + ty * 8 + i;
        if (m >= M) continue;
        int cr = scatter ? scatter[m] : m;
        float* crow = C + (size_t)cr * ldc + ncol;
        float4 o0, o1;
        o0.x = acc[i][0] + bb0.x; o0.y = acc[i][1] + bb0.y;
        o0.z = acc[i][2] + bb0.z; o0.w = acc[i][3] + bb0.w;
        o1.x = acc[i][4] + bb1.x; o1.y = acc[i][5] + bb1.y;
        o1.z = acc[i][6] + bb1.z; o1.w = acc[i][7] + bb1.w;
        if (relu) {
            o0.x = fmaxf(o0.x, 0.f); o0.y = fmaxf(o0.y, 0.f);
            o0.z = fmaxf(o0.z, 0.f); o0.w = fmaxf(o0.w, 0.f);
            o1.x = fmaxf(o1.x, 0.f); o1.y = fmaxf(o1.y, 0.f);
            o1.z = fmaxf(o1.z, 0.f); o1.w = fmaxf(o1.w, 0.f);
        }
        *(float4*)(crow)     = o0;
        *(float4*)(crow + 4) = o1;
    }
}

// ---------------------------------------------------------------------------
// tf32 tensor-core NT GEMM, cp.async double-buffered pipeline.
// Tile 128x128, BK=32, 8 warps (2Mx4N), warp tile 64x32, mma.m16n8k8.tf32.
// Smem: 2 stages x (A 128x32 + B 128x32) fp32, XOR-swizzled (granule^row&7)
// -> conflict-free LDS fragment reads. One __syncthreads per 32-K chunk.
// HMMA truncates fp32 mantissa to tf32 in HW (no explicit cvt needed).
// ---------------------------------------------------------------------------
__device__ __forceinline__ void mma_tf32(float (&d)[4], const unsigned (&a)[4],
                                         const unsigned (&b)[2]) {
    asm volatile(
        "mma.sync.aligned.m16n8k8.row.col.f32.tf32.tf32.f32 "
        "{%0,%1,%2,%3}, {%4,%5,%6,%7}, {%8,%9}, {%0,%1,%2,%3};\n"
        : "+f"(d[0]), "+f"(d[1]), "+f"(d[2]), "+f"(d[3])
        : "r"(a[0]), "r"(a[1]), "r"(a[2]), "r"(a[3]), "r"(b[0]), "r"(b[1]));
}

__device__ __forceinline__ void cp16(unsigned dst, const void* src, int nbytes) {
    asm volatile("cp.async.cg.shared.global [%0], [%1], 16, %2;"
                 :: "r"(dst), "l"(src), "r"(nbytes));
}

#define BK   32
#define ASZ  (128 * BK)                    // words per matrix per stage
#define STGB (2 * ASZ * 4)                 // bytes per stage (A+B)
#define TC_SMEM (2 * STGB)                 // 64 KB

__global__ __launch_bounds__(256, 2)
void k_gemm_tc(const float* __restrict__ A, const float* __restrict__ W,
               const float* __restrict__ bias, float* __restrict__ C,
               int M, const int* __restrict__ cntp, int K,
               const int* __restrict__ gather, const int* __restrict__ scatter,
               int ldc, int relu)
{
    if (cntp) M = *cntp;
    const int tileM = blockIdx.y * 128;
    if (tileM >= M) return;
    const int tileN = blockIdx.x * 128;

    extern __shared__ float sm[];

    const int tid  = threadIdx.x;
    const int lane = tid & 31;
    const int warp = tid >> 5;
    const int wm0 = (warp >> 2) * 64;
    const int wn0 = (warp & 3) * 32;
    const int g = lane >> 2;           // 0..7
    const int c = lane & 3;            // 0..3

    // Loader mapping: granule j (16B) within row, 4 rows per thread per matrix.
    const int j  = tid & 7;
    const int r0 = tid >> 3;           // 0..31
    const float* asrc[4]; int asz[4];
    const float* bsrc[4];
    unsigned adst[4], bdst[4];
    const unsigned smb = (unsigned)__cvta_generic_to_shared(sm);
    #pragma unroll
    for (int i = 0; i < 4; i++) {
        int r = r0 + 32 * i;           // tile row 0..127
        int m = tileM + r;
        bool v = (m < M);
        int grow = v ? (gather ? gather[m] : m) : 0;
        asrc[i] = A + (size_t)grow * K + j * 4;
        asz[i]  = v ? 16 : 0;          // zfill invalid rows
        bsrc[i] = W + (size_t)(tileN + r) * K + j * 4;
        unsigned woff = r * BK + ((j ^ (r & 7)) << 2);
        adst[i] = smb + woff * 4;
        bdst[i] = smb + (ASZ + woff) * 4;
    }

    float acc[4][4][4];
    #pragma unroll
    for (int mt = 0; mt < 4; mt++)
        #pragma unroll
        for (int nt = 0; nt < 4; nt++)
            #pragma unroll
            for (int q = 0; q < 4; q++) acc[mt][nt][q] = 0.f;

    // Preload stage 0
    #pragma unroll
    for (int i = 0; i < 4; i++) {
        cp16(adst[i], asrc[i], asz[i]);
        cp16(bdst[i], bsrc[i], 16);
    }
    asm volatile("cp.async.commit_group;" ::: "memory");

    const int nc = K / BK;
    for (int ch = 0; ch < nc; ch++) {
        asm volatile("cp.async.wait_group 0;" ::: "memory");
        __syncthreads();

        if (ch + 1 < nc) {
            const int koff = (ch + 1) * BK;
            const unsigned so = ((ch + 1) & 1) * STGB;
            #pragma unroll
            for (int i = 0; i < 4; i++) {
                cp16(adst[i] + so, asrc[i] + koff, asz[i]);
                cp16(bdst[i] + so, bsrc[i] + koff, 16);
            }
            asm volatile("cp.async.commit_group;" ::: "memory");
        }

        const float* As = sm + (ch & 1) * 2 * ASZ;
        const float* Bs = As + ASZ;

        #pragma unroll
        for (int ks = 0; ks < 4; ks++) {
            const int kb2 = ks * 2;            // kb>>2 (kb = ks*8)
            unsigned afr[4][4];
            #pragma unroll
            for (int mt = 0; mt < 4; mt++) {
                int m = wm0 + mt * 16 + g;
                int sw = m & 7;                 // (m+8)&7 == m&7
                int q0 = (kb2 ^ sw) * 4 + c;
                int q1 = ((kb2 + 1) ^ sw) * 4 + c;
                const float* pr0 = As + m * BK;
                const float* pr1 = As + (m + 8) * BK;
                afr[mt][0] = __float_as_uint(pr0[q0]);
                afr[mt][1] = __float_as_uint(pr1[q0]);
                afr[mt][2] = __float_as_uint(pr0[q1]);
                afr[mt][3] = __float_as_uint(pr1[q1]);
            }
            unsigned bfr[4][2];
            #pragma unroll
            for (int nt = 0; nt < 4; nt++) {
                int n = wn0 + nt * 8 + g;
                int sw = n & 7;
                const float* pn = Bs + n * BK;
                bfr[nt][0] = __float_as_uint(pn[(kb2 ^ sw) * 4 + c]);
                bfr[nt][1] = __float_as_uint(pn[((kb2 + 1) ^ sw) * 4 + c]);
            }
            #pragma unroll
            for (int mt = 0; mt < 4; mt++)
                #pragma unroll
                for (int nt = 0; nt < 4; nt++)
                    mma_tf32(acc[mt][nt], afr[mt], bfr[nt]);
        }
    }

    // Epilogue: bias, optional ReLU, optional row scatter. float2 stores.
    #pragma unroll
    for (int mt = 0; mt < 4; mt++) {
        int rowA = tileM + wm0 + mt * 16 + g;
        #pragma unroll
        for (int h2 = 0; h2 < 2; h2++) {
            int r = rowA + 8 * h2;
            if (r >= M) continue;
            int cr = scatter ? scatter[r] : r;
            float* crow = C + (size_t)cr * ldc;
            #pragma unroll
            for (int nt = 0; nt < 4; nt++) {
                int col = tileN + wn0 + nt * 8 + c * 2;
                float2 bb = *(const float2*)(bias + col);
                float2 o;
                o.x = acc[mt][nt][2 * h2 + 0] + bb.x;
                o.y = acc[mt][nt][2 * h2 + 1] + bb.y;
                if (relu) { o.x = fmaxf(o.x, 0.f); o.y = fmaxf(o.y, 0.f); }
                *(float2*)(crow + col) = o;
            }
        }
    }
}

// ---------------------------------------------------------------------------
extern "C" void kernel_launch(void* const* d_in, const int* in_sizes, int n_in,
                              void* d_out, int out_size)
{
    const float* h       = (const float*)d_in[0];   // [4,4096,2048]
    const float* freq    = (const float*)d_in[1];   // [4,4096]
    const float* imp     = (const float*)d_in[2];   // [4,4096]
    const float* comp1_W = (const float*)d_in[3];   // [1024,2048]
    const float* comp1_b = (const float*)d_in[4];
    const float* adpt1_W = (const float*)d_in[5];   // [1024,1024]
    const float* adpt1_b = (const float*)d_in[6];
    const float* dec1_W  = (const float*)d_in[7];   // [2048,1024]
    const float* dec1_b  = (const float*)d_in[8];
    const float* comp2_W = (const float*)d_in[9];   // [512,2048]
    const float* comp2_b = (const float*)d_in[10];
    const float* adpt2_W = (const float*)d_in[11];  // [512,512]
    const float* adpt2_b = (const float*)d_in[12];
    const float* dec2_W  = (const float*)d_in[13];  // [2048,512]
    const float* dec2_b  = (const float*)d_in[14];
    const float* sel1_W  = (const float*)d_in[15];  // [512,2048]
    const float* sel1_b  = (const float*)d_in[16];
    const float* sel2_W  = (const float*)d_in[17];  // [3,512]
    const float* sel2_b  = (const float*)d_in[18];
    float* out = (float*)d_out;

    float *bufM, *bufA, *bufB; int *idx1, *idx2, *idxR, *cnt;
    cudaGetSymbolAddress((void**)&bufM, g_bufM);
    cudaGetSymbolAddress((void**)&bufA, g_bufA);
    cudaGetSymbolAddress((void**)&bufB, g_bufB);
    cudaGetSymbolAddress((void**)&idx1, g_idx1);
    cudaGetSymbolAddress((void**)&idx2, g_idx2);
    cudaGetSymbolAddress((void**)&idxR, g_idxR);
    cudaGetSymbolAddress((void**)&cnt,  g_cnt);

    cudaFuncSetAttribute(k_gemm_tc,
        cudaFuncAttributeMaxDynamicSharedMemorySize, TC_SMEM);

    const int MAXY = TOK / 128;  // 128 m-tiles

    k_init_counters<<<1, 32>>>();

    // out = h AND bufM = modulated h, one pass
    {
        int n4 = TOK * HDIM / 4;
        k_prep<<<(n4 + 255) / 256, 256>>>(h, out, bufM, freq, imp);
    }

    // selector hidden on tensor cores (tf32): bufA [TOK,512]
    k_gemm_tc<<<dim3(512 / 128, MAXY), 256, TC_SMEM>>>(bufM, sel1_W, sel1_b, bufA,
        TOK, nullptr, HDIM, nullptr, nullptr, 512, 1);

    // fast argmax + near-tie flagging
    k_sel_fast<<<(TOK * 32 + 255) / 256, 256>>>(bufA, sel2_W, sel2_b);

    // exact fp32 hid for flagged tokens (gathered, modulated) -> bufB [nR,512]
    k_gemm128<<<dim3(512 / 128, MAXY), 256>>>(h, sel1_W, sel1_b, bufB,
        TOK, &cnt[2], HDIM, idxR, nullptr, 512, freq, imp, 1);
    k_sel_fix<<<(TOK * 32 + 255) / 256, 256>>>(bufB, sel2_W, sel2_b);

    // build branch index lists from final decisions
    k_compact<<<(TOK + 255) / 256, 256>>>();

    // ---- branch 1 (selected==1), compacted, cp.async tf32 tensor cores ----
    k_gemm_tc<<<dim3(1024 / 128, MAXY), 256, TC_SMEM>>>(h, comp1_W, comp1_b, bufB,
        TOK, &cnt[0], HDIM, idx1, nullptr, 1024, 0);
    k_gemm_tc<<<dim3(1024 / 128, MAXY), 256, TC_SMEM>>>(bufB, adpt1_W, adpt1_b, bufA,
        TOK, &cnt[0], 1024, nullptr, nullptr, 1024, 0);
    k_gemm_tc<<<dim3(2048 / 128, MAXY), 256, TC_SMEM>>>(bufA, dec1_W, dec1_b, out,
        TOK, &cnt[0], 1024, nullptr, idx1, HDIM, 0);

    // ---- branch 2 (selected==2), compacted, cp.async tf32 tensor cores ----
    k_gemm_tc<<<dim3(512 / 128, MAXY), 256, TC_SMEM>>>(h, comp2_W, comp2_b, bufB,
        TOK, &cnt[1], HDIM, idx2, nullptr, 512, 0);
    k_gemm_tc<<<dim3(512 / 128, MAXY), 256, TC_SMEM>>>(bufB, adpt2_W, adpt2_b, bufA,
        TOK, &cnt[1], 512, nullptr, nullptr, 512, 0);
    k_gemm_tc<<<dim3(2048 / 128, MAXY), 256, TC_SMEM>>>(bufA, dec2_W, dec2_b, out,
        TOK, &cnt[1], 512, nullptr, idx2, HDIM, 0);
}

// round 6
// speedup vs baseline: 3.1903x; 1.0017x over previous
#include <cuda_runtime.h>

// Problem constants (fixed shapes from reference)
#define TOK   (4 * 4096)   // B*S = 16384 tokens
#define HDIM  2048
#define TAU   0.02f        // argmax-gap threshold for exact fp32 recheck

// Scratch
__device__ float g_bufA[(size_t)TOK * 1024];  // hid / branch1 stage-2
__device__ float g_bufB[(size_t)TOK * 1024];  // recheck hid / branch1 stage-1
__device__ float g_bufC[(size_t)TOK * 512];   // branch2 stage-1
__device__ float g_bufD[(size_t)TOK * 512];   // branch2 stage-2
__device__ int   g_idx1[TOK];
__device__ int   g_idx2[TOK];
__device__ int   g_idxR[TOK];
__device__ int   g_sel[TOK];
__device__ int   g_cnt[3];   // [0]=branch1, [1]=branch2, [2]=recheck

// ---------------------------------------------------------------------------
// out = h (default for selected==0; branch scatters overwrite). Also zeroes
// the counters (block 0) so no separate init launch is needed.
__global__ void k_prep(const float* __restrict__ h, float* __restrict__ out) {
    if (blockIdx.x == 0 && threadIdx.x < 3) g_cnt[threadIdx.x] = 0;
    int i = blockIdx.x * blockDim.x + threadIdx.x;     // float4 index
    if (i < TOK * (HDIM / 4))
        ((float4*)out)[i] = ((const float4*)h)[i];
}

// ---------------------------------------------------------------------------
// Selector decision from (approximate) hid. Near-ties go to the recheck list.
__global__ void k_sel_fast(const float* __restrict__ hid,   // [TOK,512]
                           const float* __restrict__ W2,    // [3,512]
                           const float* __restrict__ b2) {
    int t = blockIdx.x * blockDim.x + threadIdx.x;
    int tok = t >> 5, lane = t & 31;
    if (tok >= TOK) return;
    const float* hrow = hid + (size_t)tok * 512;
    float s0 = 0.f, s1 = 0.f, s2 = 0.f;
    #pragma unroll 4
    for (int k = lane; k < 512; k += 32) {
        float v = hrow[k];
        s0 += v * W2[k];
        s1 += v * W2[512 + k];
        s2 += v * W2[1024 + k];
    }
    #pragma unroll
    for (int o = 16; o; o >>= 1) {
        s0 += __shfl_down_sync(0xffffffffu, s0, o);
        s1 += __shfl_down_sync(0xffffffffu, s1, o);
        s2 += __shfl_down_sync(0xffffffffu, s2, o);
    }
    if (lane == 0) {
        s0 += b2[0]; s1 += b2[1]; s2 += b2[2];
        int sel = 0; float best = s0;             // first-max rule: strict '>'
        if (s1 > best) { best = s1; sel = 1; }
        if (s2 > best) { best = s2; sel = 2; }
        g_sel[tok] = sel;
        float m1 = fmaxf(s0, fmaxf(s1, s2));
        float mn = fminf(s0, fminf(s1, s2));
        float m2 = s0 + s1 + s2 - m1 - mn;        // second largest
        if (m1 - m2 < TAU) {
            int p = atomicAdd(&g_cnt[2], 1);
            g_idxR[p] = tok;
        }
    }
}

// Final decision for rechecked tokens from exact fp32 hid rows (compacted).
__global__ void k_sel_fix(const float* __restrict__ hidx,   // [nR,512] exact
                          const float* __restrict__ W2,
                          const float* __restrict__ b2) {
    int t = blockIdx.x * blockDim.x + threadIdx.x;
    int r = t >> 5, lane = t & 31;
    if (r >= g_cnt[2]) return;
    const float* hrow = hidx + (size_t)r * 512;
    float s0 = 0.f, s1 = 0.f, s2 = 0.f;
    #pragma unroll 4
    for (int k = lane; k < 512; k += 32) {
        float v = hrow[k];
        s0 += v * W2[k];
        s1 += v * W2[512 + k];
        s2 += v * W2[1024 + k];
    }
    #pragma unroll
    for (int o = 16; o; o >>= 1) {
        s0 += __shfl_down_sync(0xffffffffu, s0, o);
        s1 += __shfl_down_sync(0xffffffffu, s1, o);
        s2 += __shfl_down_sync(0xffffffffu, s2, o);
    }
    if (lane == 0) {
        s0 += b2[0]; s1 += b2[1]; s2 += b2[2];
        int sel = 0; float best = s0;
        if (s1 > best) { best = s1; sel = 1; }
        if (s2 > best) { best = s2; sel = 2; }
        g_sel[g_idxR[r]] = sel;
    }
}

// Build branch index lists from final g_sel.
__global__ void k_compact() {
    int tok = blockIdx.x * blockDim.x + threadIdx.x;
    if (tok >= TOK) return;
    int s = g_sel[tok];
    if (s == 1)      { int p = atomicAdd(&g_cnt[0], 1); g_idx1[p] = tok; }
    else if (s == 2) { int p = atomicAdd(&g_cnt[1], 1); g_idx2[p] = tok; }
}

// ---------------------------------------------------------------------------
// fp32 SIMT NT GEMM — used only for the exact recheck (argmax must stay exact)
// ---------------------------------------------------------------------------
__global__ __launch_bounds__(256, 2)
void k_gemm128(const float* __restrict__ A, const float* __restrict__ W,
               const float* __restrict__ bias, float* __restrict__ C,
               int M, const int* __restrict__ cntp, int K,
               const int* __restrict__ gather, const int* __restrict__ scatter,
               int ldc,
               const float* __restrict__ freq, const float* __restrict__ imp,
               int relu)
{
    if (cntp) M = *cntp;
    const int tileM = blockIdx.y * 128;
    if (tileM >= M) return;
    const int tileN = blockIdx.x * 128;

    __shared__ float As[16][128];
    __shared__ float Bs[16][128];

    const int tid = threadIdx.x;
    const int tx = tid & 15;
    const int ty = tid >> 4;

    const int kk = tid & 3;
    const int r0 = tid >> 2;
    const int r1 = r0 + 64;

    const int m0 = tileM + r0;
    const int m1 = tileM + r1;
    const bool v0 = (m0 < M);
    const bool v1 = (m1 < M);
    const int gr0 = v0 ? (gather ? gather[m0] : m0) : 0;
    const int gr1 = v1 ? (gather ? gather[m1] : m1) : 0;
    const float* a0p = A + (size_t)gr0 * K;
    const float* a1p = A + (size_t)gr1 * K;
    float fr0 = 1.f, im0 = 1.f, fr1 = 1.f, im1 = 1.f;
    if (freq) { fr0 = freq[gr0]; im0 = imp[gr0]; fr1 = freq[gr1]; im1 = imp[gr1]; }

    const float* w0p = W + (size_t)(tileN + r0) * K;
    const float* w1p = W + (size_t)(tileN + r1) * K;

    float acc[8][8];
    #pragma unroll
    for (int i = 0; i < 8; i++)
        #pragma unroll
        for (int j = 0; j < 8; j++) acc[i][j] = 0.f;

    const int halfK = K >> 1;

    for (int k0 = 0; k0 < K; k0 += 16) {
        const int kc = k0 + kk * 4;
        float4 av0 = v0 ? *(const float4*)(a0p + kc) : make_float4(0.f, 0.f, 0.f, 0.f);
        float4 av1 = v1 ? *(const float4*)(a1p + kc) : make_float4(0.f, 0.f, 0.f, 0.f);
        if (freq) {
            float s0 = (kc < halfK) ? fr0 : im0;
            float s1 = (kc < halfK) ? fr1 : im1;
            av0.x *= s0; av0.y *= s0; av0.z *= s0; av0.w *= s0;
            av1.x *= s1; av1.y *= s1; av1.z *= s1; av1.w *= s1;
        }
        float4 bv0 = *(const float4*)(w0p + kc);
        float4 bv1 = *(const float4*)(w1p + kc);

        As[kk * 4 + 0][r0] = av0.x; As[kk * 4 + 1][r0] = av0.y;
        As[kk * 4 + 2][r0] = av0.z; As[kk * 4 + 3][r0] = av0.w;
        As[kk * 4 + 0][r1] = av1.x; As[kk * 4 + 1][r1] = av1.y;
        As[kk * 4 + 2][r1] = av1.z; As[kk * 4 + 3][r1] = av1.w;
        Bs[kk * 4 + 0][r0] = bv0.x; Bs[kk * 4 + 1][r0] = bv0.y;
        Bs[kk * 4 + 2][r0] = bv0.z; Bs[kk * 4 + 3][r0] = bv0.w;
        Bs[kk * 4 + 0][r1] = bv1.x; Bs[kk * 4 + 1][r1] = bv1.y;
        Bs[kk * 4 + 2][r1] = bv1.z; Bs[kk * 4 + 3][r1] = bv1.w;
        __syncthreads();

        #pragma unroll
        for (int k = 0; k < 16; k++) {
            float4 aq0 = *(const float4*)&As[k][ty * 8];
            float4 aq1 = *(const float4*)&As[k][ty * 8 + 4];
            float4 bq0 = *(const float4*)&Bs[k][tx * 8];
            float4 bq1 = *(const float4*)&Bs[k][tx * 8 + 4];
            float ar[8] = {aq0.x, aq0.y, aq0.z, aq0.w, aq1.x, aq1.y, aq1.z, aq1.w};
            float br[8] = {bq0.x, bq0.y, bq0.z, bq0.w, bq1.x, bq1.y, bq1.z, bq1.w};
            #pragma unroll
            for (int i = 0; i < 8; i++)
                #pragma unroll
                for (int j = 0; j < 8; j++)
                    acc[i][j] = fmaf(ar[i], br[j], acc[i][j]);
        }
        __syncthreads();
    }

    const int ncol = tileN + tx * 8;
    float4 bb0 = *(const float4*)(bias + ncol);
    float4 bb1 = *(const float4*)(bias + ncol + 4);
    #pragma unroll
    for (int i = 0; i < 8; i++) {
        int m = tileM + ty * 8 + i;
        if (m >= M) continue;
        int cr = scatter ? scatter[m] : m;
        float* crow = C + (size_t)cr * ldc + ncol;
        float4 o0, o1;
        o0.x = acc[i][0] + bb0.x; o0.y = acc[i][1] + bb0.y;
        o0.z = acc[i][2] + bb0.z; o0.w = acc[i][3] + bb0.w;
        o1.x = acc[i][4] + bb1.x; o1.y = acc[i][5] + bb1.y;
        o1.z = acc[i][6] + bb1.z; o1.w = acc[i][7] + bb1.w;
        if (relu) {
            o0.x = fmaxf(o0.x, 0.f); o0.y = fmaxf(o0.y, 0.f);
            o0.z = fmaxf(o0.z, 0.f); o0.w = fmaxf(o0.w, 0.f);
            o1.x = fmaxf(o1.x, 0.f); o1.y = fmaxf(o1.y, 0.f);
            o1.z = fmaxf(o1.z, 0.f); o1.w = fmaxf(o1.w, 0.f);
        }
        *(float4*)(crow)     = o0;
        *(float4*)(crow + 4) = o1;
    }
}

// ---------------------------------------------------------------------------
// tf32 tensor-core NT GEMM, 3-stage cp.async pipeline.
// Tile 128x128, BK=32, 8 warps (2Mx4N), warp tile 64x32, mma.m16n8k8.tf32.
// Smem: 3 stages x (A 128x32 + B 128x32) fp32, XOR-swizzled (granule^row&7).
// MOD: fold per-token freq/imp modulation into A-fragment loads (scale is
// uniform per 32-K chunk since K/2 is a multiple of BK).
// ---------------------------------------------------------------------------
__device__ __forceinline__ void mma_tf32(float (&d)[4], const unsigned (&a)[4],
                                         const unsigned (&b)[2]) {
    asm volatile(
        "mma.sync.aligned.m16n8k8.row.col.f32.tf32.tf32.f32 "
        "{%0,%1,%2,%3}, {%4,%5,%6,%7}, {%8,%9}, {%0,%1,%2,%3};\n"
        : "+f"(d[0]), "+f"(d[1]), "+f"(d[2]), "+f"(d[3])
        : "r"(a[0]), "r"(a[1]), "r"(a[2]), "r"(a[3]), "r"(b[0]), "r"(b[1]));
}

__device__ __forceinline__ void cp16(unsigned dst, const void* src, int nbytes) {
    asm volatile("cp.async.cg.shared.global [%0], [%1], 16, %2;"
                 :: "r"(dst), "l"(src), "r"(nbytes));
}

#define BK   32
#define ASZ  (128 * BK)                    // words per matrix per stage
#define STGW (2 * ASZ)                     // words per stage (A+B)
#define STGB (STGW * 4)                    // bytes per stage
#define TC_SMEM (3 * STGB)                 // 96 KB

template<bool MOD>
__device__ __forceinline__ void gemm_tc_body(
    const float* __restrict__ A, const float* __restrict__ W,
    const float* __restrict__ bias, float* __restrict__ C,
    int M, int K, const int* __restrict__ gather,
    const int* __restrict__ scatter, int ldc, int relu,
    const float* __restrict__ freq, const float* __restrict__ imp,
    int tileM, int tileN)
{
    extern __shared__ float sm[];

    const int tid  = threadIdx.x;
    const int lane = tid & 31;
    const int warp = tid >> 5;
    const int wm0 = (warp >> 2) * 64;
    const int wn0 = (warp & 3) * 32;
    const int g = lane >> 2;           // 0..7
    const int c = lane & 3;            // 0..3

    // Loader mapping: granule j (16B) within row, 4 rows per thread per matrix.
    const int j  = tid & 7;
    const int r0 = tid >> 3;           // 0..31
    const float* asrc[4]; int asz[4];
    const float* bsrc[4];
    unsigned adst[4], bdst[4];
    const unsigned smb = (unsigned)__cvta_generic_to_shared(sm);
    #pragma unroll
    for (int i = 0; i < 4; i++) {
        int r = r0 + 32 * i;           // tile row 0..127
        int m = tileM + r;
        bool v = (m < M);
        int grow = v ? (gather ? gather[m] : m) : 0;
        asrc[i] = A + (size_t)grow * K + j * 4;
        asz[i]  = v ? 16 : 0;          // zfill invalid rows
        bsrc[i] = W + (size_t)(tileN + r) * K + j * 4;
        unsigned woff = r * BK + ((j ^ (r & 7)) << 2);
        adst[i] = smb + woff * 4;
        bdst[i] = smb + (ASZ + woff) * 4;
    }

    // Per-row modulation scales (selector path only). Rows are in-range:
    // selector runs at M = TOK with exact grid.
    float sfr[4][2], sim[4][2];
    if (MOD) {
        #pragma unroll
        for (int mt = 0; mt < 4; mt++) {
            int rA = tileM + wm0 + mt * 16 + g;
            int rB = rA + 8;
            sfr[mt][0] = freq[rA]; sfr[mt][1] = freq[rB];
            sim[mt][0] = imp[rA];  sim[mt][1] = imp[rB];
        }
    }

    float acc[4][4][4];
    #pragma unroll
    for (int mt = 0; mt < 4; mt++)
        #pragma unroll
        for (int nt = 0; nt < 4; nt++)
            #pragma unroll
            for (int q = 0; q < 4; q++) acc[mt][nt][q] = 0.f;

    const int nc = K / BK;

    // Preload stages 0 and 1 (two committed groups)
    #pragma unroll
    for (int i = 0; i < 4; i++) {
        cp16(adst[i], asrc[i], asz[i]);
        cp16(bdst[i], bsrc[i], 16);
    }
    asm volatile("cp.async.commit_group;" ::: "memory");
    if (nc > 1) {
        #pragma unroll
        for (int i = 0; i < 4; i++) {
            cp16(adst[i] + STGB, asrc[i] + BK, asz[i]);
            cp16(bdst[i] + STGB, bsrc[i] + BK, 16);
        }
    }
    asm volatile("cp.async.commit_group;" ::: "memory");

    for (int ch = 0; ch < nc; ch++) {
        // With one (possibly empty) commit per iteration, the group loading
        // chunk ch is always second-from-last here -> wait_group 1 suffices.
        asm volatile("cp.async.wait_group 1;" ::: "memory");
        __syncthreads();

        if (ch + 2 < nc) {
            const int koff = (ch + 2) * BK;
            const unsigned so = ((ch + 2) % 3) * STGB;
            #pragma unroll
            for (int i = 0; i < 4; i++) {
                cp16(adst[i] + so, asrc[i] + koff, asz[i]);
                cp16(bdst[i] + so, bsrc[i] + koff, 16);
            }
        }
        asm volatile("cp.async.commit_group;" ::: "memory");

        const float* As = sm + (ch % 3) * STGW;
        const float* Bs = As + ASZ;
        const bool useFr = MOD && (ch * BK * 2 < K);   // first half of K

        #pragma unroll
        for (int ks = 0; ks < 4; ks++) {
            const int kb2 = ks * 2;            // granule index pair base
            unsigned afr[4][4];
            #pragma unroll
            for (int mt = 0; mt < 4; mt++) {
                int m = wm0 + mt * 16 + g;
                int sw = m & 7;                 // (m+8)&7 == m&7
                int q0 = (kb2 ^ sw) * 4 + c;
                int q1 = ((kb2 + 1) ^ sw) * 4 + c;
                const float* pr0 = As + m * BK;
                const float* pr1 = As + (m + 8) * BK;
                if (MOD) {
                    float s0 = useFr ? sfr[mt][0] : sim[mt][0];
                    float s1 = useFr ? sfr[mt][1] : sim[mt][1];
                    afr[mt][0] = __float_as_uint(pr0[q0] * s0);
                    afr[mt][1] = __float_as_uint(pr1[q0] * s1);
                    afr[mt][2] = __float_as_uint(pr0[q1] * s0);
                    afr[mt][3] = __float_as_uint(pr1[q1] * s1);
                } else {
                    afr[mt][0] = __float_as_uint(pr0[q0]);
                    afr[mt][1] = __float_as_uint(pr1[q0]);
                    afr[mt][2] = __float_as_uint(pr0[q1]);
                    afr[mt][3] = __float_as_uint(pr1[q1]);
                }
            }
            unsigned bfr[4][2];
            #pragma unroll
            for (int nt = 0; nt < 4; nt++) {
                int n = wn0 + nt * 8 + g;
                int sw = n & 7;
                const float* pn = Bs + n * BK;
                bfr[nt][0] = __float_as_uint(pn[(kb2 ^ sw) * 4 + c]);
                bfr[nt][1] = __float_as_uint(pn[((kb2 + 1) ^ sw) * 4 + c]);
            }
            #pragma unroll
            for (int mt = 0; mt < 4; mt++)
                #pragma unroll
                for (int nt = 0; nt < 4; nt++)
                    mma_tf32(acc[mt][nt], afr[mt], bfr[nt]);
        }
    }

    // Epilogue: bias, optional ReLU, optional row scatter. float2 stores.
    #pragma unroll
    for (int mt = 0; mt < 4; mt++) {
        int rowA = tileM + wm0 + mt * 16 + g;
        #pragma unroll
        for (int h2 = 0; h2 < 2; h2++) {
            int r = rowA + 8 * h2;
            if (r >= M) continue;
            int cr = scatter ? scatter[r] : r;
            float* crow = C + (size_t)cr * ldc;
            #pragma unroll
            for (int nt = 0; nt < 4; nt++) {
                int col = tileN + wn0 + nt * 8 + c * 2;
                float2 bb = *(const float2*)(bias + col);
                float2 o;
                o.x = acc[mt][nt][2 * h2 + 0] + bb.x;
                o.y = acc[mt][nt][2 * h2 + 1] + bb.y;
                if (relu) { o.x = fmaxf(o.x, 0.f); o.y = fmaxf(o.y, 0.f); }
                *(float2*)(crow + col) = o;
            }
        }
    }
}

// Selector GEMM: modulation folded in, ReLU, static M = TOK.
__global__ __launch_bounds__(256, 2)
void k_gemm_sel(const float* __restrict__ A, const float* __restrict__ W,
                const float* __restrict__ bias, float* __restrict__ C,
                int K, int ldc,
                const float* __restrict__ freq, const float* __restrict__ imp)
{
    gemm_tc_body<true>(A, W, bias, C, TOK, K, nullptr, nullptr, ldc, 1,
                       freq, imp, blockIdx.y * 128, blockIdx.x * 128);
}

// Dual-branch GEMM: blockIdx.z selects the job (branch1 / branch2).
struct Job {
    const float* A; const float* W; const float* bias; float* C;
    const int* cntp; int K; int N;
    const int* gather; const int* scatter; int ldc;
};

__global__ __launch_bounds__(256, 2)
void k_gemm_dual(Job j0, Job j1)
{
    const Job& j = (blockIdx.z == 0) ? j0 : j1;
    int M = *j.cntp;
    int tileM = blockIdx.y * 128;
    if (tileM >= M) return;
    int tileN = blockIdx.x * 128;
    if (tileN >= j.N) return;
    gemm_tc_body<false>(j.A, j.W, j.bias, j.C, M, j.K, j.gather, j.scatter,
                        j.ldc, 0, nullptr, nullptr, tileM, tileN);
}

// ---------------------------------------------------------------------------
extern "C" void kernel_launch(void* const* d_in, const int* in_sizes, int n_in,
                              void* d_out, int out_size)
{
    const float* h       = (const float*)d_in[0];   // [4,4096,2048]
    const float* freq    = (const float*)d_in[1];   // [4,4096]
    const float* imp     = (const float*)d_in[2];   // [4,4096]
    const float* comp1_W = (const float*)d_in[3];   // [1024,2048]
    const float* comp1_b = (const float*)d_in[4];
    const float* adpt1_W = (const float*)d_in[5];   // [1024,1024]
    const float* adpt1_b = (const float*)d_in[6];
    const float* dec1_W  = (const float*)d_in[7];   // [2048,1024]
    const float* dec1_b  = (const float*)d_in[8];
    const float* comp2_W = (const float*)d_in[9];   // [512,2048]
    const float* comp2_b = (const float*)d_in[10];
    const float* adpt2_W = (const float*)d_in[11];  // [512,512]
    const float* adpt2_b = (const float*)d_in[12];
    const float* dec2_W  = (const float*)d_in[13];  // [2048,512]
    const float* dec2_b  = (const float*)d_in[14];
    const float* sel1_W  = (const float*)d_in[15];  // [512,2048]
    const float* sel1_b  = (const float*)d_in[16];
    const float* sel2_W  = (const float*)d_in[17];  // [3,512]
    const float* sel2_b  = (const float*)d_in[18];
    float* out = (float*)d_out;

    float *bufA, *bufB, *bufC, *bufD; int *idx1, *idx2, *idxR, *cnt;
    cudaGetSymbolAddress((void**)&bufA, g_bufA);
    cudaGetSymbolAddress((void**)&bufB, g_bufB);
    cudaGetSymbolAddress((void**)&bufC, g_bufC);
    cudaGetSymbolAddress((void**)&bufD, g_bufD);
    cudaGetSymbolAddress((void**)&idx1, g_idx1);
    cudaGetSymbolAddress((void**)&idx2, g_idx2);
    cudaGetSymbolAddress((void**)&idxR, g_idxR);
    cudaGetSymbolAddress((void**)&cnt,  g_cnt);

    cudaFuncSetAttribute(k_gemm_sel,
        cudaFuncAttributeMaxDynamicSharedMemorySize, TC_SMEM);
    cudaFuncSetAttribute(k_gemm_dual,
        cudaFuncAttributeMaxDynamicSharedMemorySize, TC_SMEM);

    const int MAXY = TOK / 128;  // 128 m-tiles

    // out = h ; counters zeroed by block 0
    {
        int n4 = TOK * HDIM / 4;
        k_prep<<<(n4 + 255) / 256, 256>>>(h, out);
    }

    // selector hidden on tensor cores, modulation fused: bufA [TOK,512]
    k_gemm_sel<<<dim3(512 / 128, MAXY), 256, TC_SMEM>>>(
        h, sel1_W, sel1_b, bufA, HDIM, 512, freq, imp);

    // fast argmax + near-tie flagging
    k_sel_fast<<<(TOK * 32 + 255) / 256, 256>>>(bufA, sel2_W, sel2_b);

    // exact fp32 hid for flagged tokens (gathered, modulated) -> bufB [nR,512]
    k_gemm128<<<dim3(512 / 128, MAXY), 256>>>(h, sel1_W, sel1_b, bufB,
        TOK, &cnt[2], HDIM, idxR, nullptr, 512, freq, imp, 1);
    k_sel_fix<<<(TOK * 32 + 255) / 256, 256>>>(bufB, sel2_W, sel2_b);

    // build branch index lists from final decisions
    k_compact<<<(TOK + 255) / 256, 256>>>();

    // ---- both branches, pairwise-merged GEMMs (z = branch) ----
    {   // compress: b1 h->bufB [n1,1024] ; b2 h->bufC [n2,512]
        Job j0 = {h, comp1_W, comp1_b, bufB, &cnt[0], HDIM, 1024, idx1, nullptr, 1024};
        Job j1 = {h, comp2_W, comp2_b, bufC, &cnt[1], HDIM,  512, idx2, nullptr,  512};
        k_gemm_dual<<<dim3(8, MAXY, 2), 256, TC_SMEM>>>(j0, j1);
    }
    {   // adapt: b1 bufB->bufA ; b2 bufC->bufD
        Job j0 = {bufB, adpt1_W, adpt1_b, bufA, &cnt[0], 1024, 1024, nullptr, nullptr, 1024};
        Job j1 = {bufC, adpt2_W, adpt2_b, bufD, &cnt[1],  512,  512, nullptr, nullptr,  512};
        k_gemm_dual<<<dim3(8, MAXY, 2), 256, TC_SMEM>>>(j0, j1);
    }
    {   // decompress + scatter into out
        Job j0 = {bufA, dec1_W, dec1_b, out, &cnt[0], 1024, HDIM, nullptr, idx1, HDIM};
        Job j1 = {bufD, dec2_W, dec2_b, out, &cnt[1],  512, HDIM, nullptr, idx2, HDIM};
        k_gemm_dual<<<dim3(16, MAXY, 2), 256, TC_SMEM>>>(j0, j1);
    }
}